// round 1
// baseline (speedup 1.0000x reference)
#include <cuda_runtime.h>

#define Bn 1024
#define Cc 128
#define Dd 16
#define Ss 4
#define NK3 23
#define NK2 5
#define NK1 2
#define NM3 816   // # monomials i<=j<=l, D=16 -> C(18,3)
#define NM2 136   // # pairs i<=j
#define OT 4      // total output irrep components: 1 (0e) + 3 (1o)

// ---------------- scratch (device globals; no allocation allowed) ----------------
__device__ float  g_u3s[OT*NM3*NK3];     // symmetrized u3 basis
__device__ float  g_u2s[OT*NM2*NK2];     // symmetrized u2 basis
__device__ float4 g_uw3s[Ss*Cc*NM3];     // per-(species,channel) weighted basis, float4 over o
__device__ float4 g_uw2s[Ss*Cc*NM2];
__device__ float4 g_uw1s[Ss*Cc*Dd];
__device__ float  g_Y[OT*Cc*Bn];         // y[o][c][b]
__device__ int    g_count[Ss];
__device__ int    g_list[Ss*Bn];

// ---------------- species grouping ----------------
__global__ void k_reset() { if (threadIdx.x < Ss) g_count[threadIdx.x] = 0; }

__global__ void k_species(const int* __restrict__ sp) {
    int b = blockIdx.x*blockDim.x + threadIdx.x;
    if (b < Bn) {
        int e = sp[b];
        int pos = atomicAdd(&g_count[e], 1);
        g_list[e*Bn + pos] = b;
    }
}

// ---------------- symmetrize u3 over (i,j,l) ----------------
__device__ __forceinline__ float u3at(const float* __restrict__ u3_0,
                                      const float* __restrict__ u3_1,
                                      int o, int a, int b, int c, int k) {
    if (o == 0) return u3_0[((a*Dd + b)*Dd + c)*NK3 + k];
    return u3_1[((((o-1)*Dd + a)*Dd + b)*Dd + c)*NK3 + k];
}

__global__ void k_sym3(const float* __restrict__ u3_0, const float* __restrict__ u3_1) {
    int tid = blockIdx.x*blockDim.x + threadIdx.x;   // 4*4096 threads
    int o = tid >> 12;
    int r = tid & 4095;
    int i = (r >> 8) & 15, j = (r >> 4) & 15, l = r & 15;
    if (o >= OT || i > j || j > l) return;
    // lexicographic index of sorted monomial (i,j,l)
    int m = 0;
    for (int a = 0; a < i; a++) m += (Dd-a)*(Dd-a+1)/2;
    for (int b2 = i; b2 < j; b2++) m += (Dd-b2);
    m += l - j;
    int P[6][3] = {{i,j,l},{i,l,j},{j,i,l},{j,l,i},{l,i,j},{l,j,i}};
    bool use[6];
    #pragma unroll
    for (int p = 0; p < 6; p++) {
        use[p] = true;
        for (int q = 0; q < p; q++)
            if (P[q][0]==P[p][0] && P[q][1]==P[p][1] && P[q][2]==P[p][2]) { use[p] = false; break; }
    }
    for (int k = 0; k < NK3; k++) {
        float s = 0.f;
        #pragma unroll
        for (int p = 0; p < 6; p++)
            if (use[p]) s += u3at(u3_0, u3_1, o, P[p][0], P[p][1], P[p][2], k);
        g_u3s[(o*NM3 + m)*NK3 + k] = s;
    }
}

__global__ void k_sym2(const float* __restrict__ u2_0, const float* __restrict__ u2_1) {
    int tid = blockIdx.x*blockDim.x + threadIdx.x;   // 4*256 threads
    int o = tid >> 8;
    int r = tid & 255;
    int i = (r >> 4) & 15, j = r & 15;
    if (o >= OT || i > j) return;
    int m = 0;
    for (int a = 0; a < i; a++) m += (Dd - a);
    m += j - i;
    for (int k = 0; k < NK2; k++) {
        float s;
        if (o == 0) {
            s = u2_0[(i*Dd + j)*NK2 + k];
            if (i != j) s += u2_0[(j*Dd + i)*NK2 + k];
        } else {
            s = u2_1[(((o-1)*Dd + i)*Dd + j)*NK2 + k];
            if (i != j) s += u2_1[(((o-1)*Dd + j)*Dd + i)*NK2 + k];
        }
        g_u2s[(o*NM2 + m)*NK2 + k] = s;
    }
}

// ---------------- fold species weights into bases ----------------
__global__ void k_fold3(const float* __restrict__ w3) {
    int tid = blockIdx.x*blockDim.x + threadIdx.x;
    if (tid >= Ss*Cc*NM3) return;
    int m = tid % NM3; int ec = tid / NM3;
    int c = ec % Cc;   int e  = ec / Cc;
    const float* u0  = g_u3s + (0*NM3 + m)*NK3;
    const float* u1p = g_u3s + (1*NM3 + m)*NK3;
    const float* u2p = g_u3s + (2*NM3 + m)*NK3;
    const float* u3p = g_u3s + (3*NM3 + m)*NK3;
    const float* w0  = w3 + ((0*Ss + e)*NK3)*Cc + c;   // set 0
    const float* w1v = w3 + ((1*Ss + e)*NK3)*Cc + c;   // set 1
    float s0=0.f, s1=0.f, s2=0.f, s3=0.f;
    #pragma unroll
    for (int k = 0; k < NK3; k++) {
        float a = w0[k*Cc], b = w1v[k*Cc];
        s0 += u0[k]*a; s1 += u1p[k]*b; s2 += u2p[k]*b; s3 += u3p[k]*b;
    }
    g_uw3s[tid] = make_float4(s0,s1,s2,s3);
}

__global__ void k_fold2(const float* __restrict__ w2) {
    int tid = blockIdx.x*blockDim.x + threadIdx.x;
    if (tid >= Ss*Cc*NM2) return;
    int m = tid % NM2; int ec = tid / NM2;
    int c = ec % Cc;   int e  = ec / Cc;
    const float* u0  = g_u2s + (0*NM2 + m)*NK2;
    const float* u1p = g_u2s + (1*NM2 + m)*NK2;
    const float* u2p = g_u2s + (2*NM2 + m)*NK2;
    const float* u3p = g_u2s + (3*NM2 + m)*NK2;
    const float* w0  = w2 + ((0*Ss + e)*NK2)*Cc + c;
    const float* w1v = w2 + ((1*Ss + e)*NK2)*Cc + c;
    float s0=0.f, s1=0.f, s2=0.f, s3=0.f;
    #pragma unroll
    for (int k = 0; k < NK2; k++) {
        float a = w0[k*Cc], b = w1v[k*Cc];
        s0 += u0[k]*a; s1 += u1p[k]*b; s2 += u2p[k]*b; s3 += u3p[k]*b;
    }
    g_uw2s[tid] = make_float4(s0,s1,s2,s3);
}

__global__ void k_fold1(const float* __restrict__ u1_0, const float* __restrict__ u1_1,
                        const float* __restrict__ w1) {
    int tid = blockIdx.x*blockDim.x + threadIdx.x;
    if (tid >= Ss*Cc*Dd) return;
    int i = tid % Dd; int ec = tid / Dd;
    int c = ec % Cc;  int e  = ec / Cc;
    float s[OT];
    #pragma unroll
    for (int o = 0; o < OT; o++) {
        int set = (o == 0) ? 0 : 1;
        float acc = 0.f;
        #pragma unroll
        for (int k = 0; k < NK1; k++) {
            float uv = (o == 0) ? u1_0[i*NK1 + k]
                                : u1_1[(((o-1)*Dd) + i)*NK1 + k];
            acc += uv * w1[((set*Ss + e)*NK1 + k)*Cc + c];
        }
        s[o] = acc;
    }
    g_uw1s[tid] = make_float4(s[0], s[1], s[2], s[3]);
}

// ---------------- main symmetric-contraction kernel ----------------
__global__ void __launch_bounds__(128) k_main(const float* __restrict__ nf) {
    __shared__ float4 su3[NM3];     // 13056 B
    __shared__ float4 su2[NM2];     //  2176 B
    __shared__ float4 su1[Dd];      //   256 B
    __shared__ float  sx[128*17];   //  8704 B, stride-17 -> bank-conflict-free
    int c = blockIdx.x, e = blockIdx.y, half = blockIdx.z;
    int t = threadIdx.x;
    int ec = e*Cc + c;
    for (int idx = t; idx < NM3; idx += 128) su3[idx] = g_uw3s[ec*NM3 + idx];
    for (int idx = t; idx < NM2; idx += 128) su2[idx] = g_uw2s[ec*NM2 + idx];
    if (t < Dd) su1[t] = g_uw1s[ec*Dd + t];
    __syncthreads();
    int n = g_count[e];
    float* xp = sx + t*17;
    for (int base = half*128; base < n; base += 256) {
        int li = base + t;
        if (li >= n) continue;            // no barriers below: safe divergence
        int b = g_list[e*Bn + li];
        const float4* src = reinterpret_cast<const float4*>(nf + (b*Cc + c)*Dd);
        float4 v0 = src[0], v1 = src[1], v2 = src[2], v3 = src[3];
        xp[0]=v0.x;  xp[1]=v0.y;  xp[2]=v0.z;  xp[3]=v0.w;
        xp[4]=v1.x;  xp[5]=v1.y;  xp[6]=v1.z;  xp[7]=v1.w;
        xp[8]=v2.x;  xp[9]=v2.y;  xp[10]=v2.z; xp[11]=v2.w;
        xp[12]=v3.x; xp[13]=v3.y; xp[14]=v3.z; xp[15]=v3.w;
        float a0=0.f, a1=0.f, a2=0.f, a3=0.f;
        int m3 = 0, m2 = 0;
        for (int i = 0; i < Dd; i++) {
            float xi = xp[i];
            float4 u1r = su1[i];
            a0 += u1r.x*xi; a1 += u1r.y*xi; a2 += u1r.z*xi; a3 += u1r.w*xi;
            for (int j = i; j < Dd; j++) {
                float xx = xi * xp[j];
                float4 u2r = su2[m2++];
                a0 += u2r.x*xx; a1 += u2r.y*xx; a2 += u2r.z*xx; a3 += u2r.w*xx;
                #pragma unroll 4
                for (int l = j; l < Dd; l++) {
                    float4 u = su3[m3++];          // broadcast LDS.128
                    float mm = xx * xp[l];
                    a0 += u.x*mm; a1 += u.y*mm; a2 += u.z*mm; a3 += u.w*mm;
                }
            }
        }
        g_Y[(0*Cc + c)*Bn + b] = a0;
        g_Y[(1*Cc + c)*Bn + b] = a1;
        g_Y[(2*Cc + c)*Bn + b] = a2;
        g_Y[(3*Cc + c)*Bn + b] = a3;
    }
}

// ---------------- final equivariant linear (channel mix) ----------------
__global__ void __launch_bounds__(256) k_linear(const float* __restrict__ wlin,
                                                float* __restrict__ out) {
    __shared__ float Ys[32][64];
    __shared__ float Ws[32][128];
    int o  = blockIdx.y;
    int b0 = blockIdx.x * 64;
    int set = (o == 0) ? 0 : 1;
    int t  = threadIdx.x;
    int tb = t & 63;
    int tg = t >> 6;
    float acc[32];
    #pragma unroll
    for (int q = 0; q < 32; q++) acc[q] = 0.f;
    for (int c0 = 0; c0 < Cc; c0 += 32) {
        __syncthreads();
        for (int idx = t; idx < 32*64; idx += 256) {
            int cc = idx >> 6, bb = idx & 63;
            Ys[cc][bb] = g_Y[(o*Cc + c0 + cc)*Bn + b0 + bb];
        }
        for (int idx = t; idx < 32*128; idx += 256) {
            int cc = idx >> 7, nn = idx & 127;
            Ws[cc][nn] = wlin[(set*Cc + c0 + cc)*Cc + nn];
        }
        __syncthreads();
        #pragma unroll
        for (int cc = 0; cc < 32; cc++) {
            float a = Ys[cc][tb];
            #pragma unroll
            for (int q = 0; q < 32; q++)
                acc[q] += a * Ws[cc][tg*32 + q];
        }
    }
    const float scale = 0.08838834764831845f;    // 1/sqrt(128)
    int b = b0 + tb;
    if (o == 0) {
        #pragma unroll
        for (int q = 0; q < 32; q++)
            out[b*512 + tg*32 + q] = acc[q]*scale;
    } else {
        int op = o - 1;
        #pragma unroll
        for (int q = 0; q < 32; q++)
            out[b*512 + 128 + (tg*32 + q)*3 + op] = acc[q]*scale;
    }
}

// ---------------- launch ----------------
extern "C" void kernel_launch(void* const* d_in, const int* in_sizes, int n_in,
                              void* d_out, int out_size) {
    const float* nf   = (const float*)d_in[0];
    const float* u3_0 = (const float*)d_in[1];
    const float* u3_1 = (const float*)d_in[2];
    const float* u2_0 = (const float*)d_in[3];
    const float* u2_1 = (const float*)d_in[4];
    const float* u1_0 = (const float*)d_in[5];
    const float* u1_1 = (const float*)d_in[6];
    const float* w3   = (const float*)d_in[7];
    const float* w2   = (const float*)d_in[8];
    const float* w1   = (const float*)d_in[9];
    const float* wl   = (const float*)d_in[10];
    const int*   sp   = (const int*)d_in[11];
    float* out = (float*)d_out;

    k_reset<<<1, 32>>>();
    k_species<<<4, 256>>>(sp);
    k_sym3<<<64, 256>>>(u3_0, u3_1);
    k_sym2<<<4, 256>>>(u2_0, u2_1);
    k_fold3<<<(Ss*Cc*NM3 + 255)/256, 256>>>(w3);
    k_fold2<<<(Ss*Cc*NM2 + 255)/256, 256>>>(w2);
    k_fold1<<<(Ss*Cc*Dd  + 255)/256, 256>>>(u1_0, u1_1, w1);
    k_main<<<dim3(Cc, Ss, 2), 128>>>(nf);
    k_linear<<<dim3(Bn/64, 4), 256>>>(wl, out);
}

// round 2
// speedup vs baseline: 1.5355x; 1.5355x over previous
#include <cuda_runtime.h>

#define Bn 1024
#define Cc 128
#define Dd 16
#define Ss 4
#define NK3 23
#define NK2 5
#define NK1 2
#define NM3 816   // # monomials i<=j<=l, D=16 -> C(18,3)
#define NM2 136   // # pairs i<=j
#define OT 4      // total output irrep components: 1 (0e) + 3 (1o)

typedef unsigned long long u64;

// ---------------- scratch (device globals; no allocation allowed) ----------------
__device__ float  g_u3s[OT*NK3*NM3];     // symmetrized u3 basis, layout [o][k][m]
__device__ float  g_u2s[OT*NK2*NM2];     // symmetrized u2 basis, layout [o][k][m]
__device__ float4 g_uw3s[Ss*Cc*NM3];     // per-(species,channel) weighted basis, float4 over o
__device__ float4 g_uw2s[Ss*Cc*NM2];
__device__ float4 g_uw1s[Ss*Cc*Dd];
__device__ float  g_Y[OT*Cc*Bn];         // y[o][c][b]
__device__ int    g_count[Ss];
__device__ int    g_list[Ss*Bn];

// ---------------- fused prep: species sort + symmetrize u3/u2 ----------------
__device__ __forceinline__ float u3at(const float* __restrict__ u3_0,
                                      const float* __restrict__ u3_1,
                                      int o, int a, int b, int c, int k) {
    if (o == 0) return u3_0[((a*Dd + b)*Dd + c)*NK3 + k];
    return u3_1[((((o-1)*Dd + a)*Dd + b)*Dd + c)*NK3 + k];
}

__global__ void k_prep(const int* __restrict__ sp,
                       const float* __restrict__ u3_0, const float* __restrict__ u3_1,
                       const float* __restrict__ u2_0, const float* __restrict__ u2_1) {
    int blk = blockIdx.x;
    int t = threadIdx.x;                 // 256 threads
    if (blk == 0) {
        // species counting-sort (single block so reset+add are ordered)
        if (t < Ss) g_count[t] = 0;
        __syncthreads();
        for (int b = t; b < Bn; b += 256) {
            int e = sp[b];
            int pos = atomicAdd(&g_count[e], 1);
            g_list[e*Bn + pos] = b;
        }
    } else if (blk <= 64) {
        // symmetrize u3 -> g_u3s[o][k][m]
        int tid = (blk-1)*256 + t;       // 0..16383 = 4 * 4096
        int o = tid >> 12;
        int r = tid & 4095;
        int i = (r >> 8) & 15, j = (r >> 4) & 15, l = r & 15;
        if (i > j || j > l) return;
        int m = 0;
        for (int a = 0; a < i; a++) m += (Dd-a)*(Dd-a+1)/2;
        for (int b2 = i; b2 < j; b2++) m += (Dd-b2);
        m += l - j;
        int P[6][3] = {{i,j,l},{i,l,j},{j,i,l},{j,l,i},{l,i,j},{l,j,i}};
        bool use[6];
        #pragma unroll
        for (int p = 0; p < 6; p++) {
            use[p] = true;
            for (int q = 0; q < p; q++)
                if (P[q][0]==P[p][0] && P[q][1]==P[p][1] && P[q][2]==P[p][2]) { use[p] = false; break; }
        }
        for (int k = 0; k < NK3; k++) {
            float s = 0.f;
            #pragma unroll
            for (int p = 0; p < 6; p++)
                if (use[p]) s += u3at(u3_0, u3_1, o, P[p][0], P[p][1], P[p][2], k);
            g_u3s[(o*NK3 + k)*NM3 + m] = s;
        }
    } else {
        // symmetrize u2 -> g_u2s[o][k][m]
        int tid = (blk-65)*256 + t;      // 0..1023 = 4 * 256
        if (tid >= OT*256) return;
        int o = tid >> 8;
        int r = tid & 255;
        int i = (r >> 4) & 15, j = r & 15;
        if (i > j) return;
        int m = 0;
        for (int a = 0; a < i; a++) m += (Dd - a);
        m += j - i;
        for (int k = 0; k < NK2; k++) {
            float s;
            if (o == 0) {
                s = u2_0[(i*Dd + j)*NK2 + k];
                if (i != j) s += u2_0[(j*Dd + i)*NK2 + k];
            } else {
                s = u2_1[(((o-1)*Dd + i)*Dd + j)*NK2 + k];
                if (i != j) s += u2_1[(((o-1)*Dd + j)*Dd + i)*NK2 + k];
            }
            g_u2s[(o*NK2 + k)*NM2 + m] = s;
        }
    }
}

// ---------------- fused fold: species weights into bases (coalesced u reads) ----------------
#define F3_BLKS (Ss*Cc*NM3/256)   // 1632
#define F2_BLKS (Ss*Cc*NM2/256)   // 272
#define F1_BLKS (Ss*Cc*Dd/256)    // 32

__global__ void k_fold(const float* __restrict__ w3, const float* __restrict__ w2,
                       const float* __restrict__ u1_0, const float* __restrict__ u1_1,
                       const float* __restrict__ w1) {
    int blk = blockIdx.x;
    int t = threadIdx.x;
    if (blk < F3_BLKS) {
        int tid = blk*256 + t;
        int m = tid % NM3; int ec = tid / NM3;
        int c = ec % Cc;   int e  = ec / Cc;
        const float* w0  = w3 + ((0*Ss + e)*NK3)*Cc + c;
        const float* w1v = w3 + ((1*Ss + e)*NK3)*Cc + c;
        float s0=0.f, s1=0.f, s2=0.f, s3=0.f;
        #pragma unroll
        for (int k = 0; k < NK3; k++) {
            float a = __ldg(w0 + k*Cc), b = __ldg(w1v + k*Cc);   // warp-uniform
            s0 += g_u3s[(0*NK3 + k)*NM3 + m]*a;                  // lane-coalesced
            s1 += g_u3s[(1*NK3 + k)*NM3 + m]*b;
            s2 += g_u3s[(2*NK3 + k)*NM3 + m]*b;
            s3 += g_u3s[(3*NK3 + k)*NM3 + m]*b;
        }
        g_uw3s[tid] = make_float4(s0,s1,s2,s3);
    } else if (blk < F3_BLKS + F2_BLKS) {
        int tid = (blk - F3_BLKS)*256 + t;
        int m = tid % NM2; int ec = tid / NM2;
        int c = ec % Cc;   int e  = ec / Cc;
        const float* w0  = w2 + ((0*Ss + e)*NK2)*Cc + c;
        const float* w1v = w2 + ((1*Ss + e)*NK2)*Cc + c;
        float s0=0.f, s1=0.f, s2=0.f, s3=0.f;
        #pragma unroll
        for (int k = 0; k < NK2; k++) {
            float a = __ldg(w0 + k*Cc), b = __ldg(w1v + k*Cc);
            s0 += g_u2s[(0*NK2 + k)*NM2 + m]*a;
            s1 += g_u2s[(1*NK2 + k)*NM2 + m]*b;
            s2 += g_u2s[(2*NK2 + k)*NM2 + m]*b;
            s3 += g_u2s[(3*NK2 + k)*NM2 + m]*b;
        }
        g_uw2s[tid] = make_float4(s0,s1,s2,s3);
    } else {
        int tid = (blk - F3_BLKS - F2_BLKS)*256 + t;
        int i = tid % Dd; int ec = tid / Dd;
        int c = ec % Cc;  int e  = ec / Cc;
        float s[OT];
        #pragma unroll
        for (int o = 0; o < OT; o++) {
            int set = (o == 0) ? 0 : 1;
            float acc = 0.f;
            #pragma unroll
            for (int k = 0; k < NK1; k++) {
                float uv = (o == 0) ? u1_0[i*NK1 + k]
                                    : u1_1[(((o-1)*Dd) + i)*NK1 + k];
                acc += uv * w1[((set*Ss + e)*NK1 + k)*Cc + c];
            }
            s[o] = acc;
        }
        g_uw1s[tid] = make_float4(s[0], s[1], s[2], s[3]);
    }
}

// ---------------- main symmetric-contraction kernel (packed f32x2) ----------------
#define FMA2(acc, a, b) asm("fma.rn.f32x2 %0, %1, %2, %0;" : "+l"(acc) : "l"(a), "l"(b))
#define MUL2(d, a, b)   asm("mul.rn.f32x2 %0, %1, %2;" : "=l"(d) : "l"(a), "l"(b))

__global__ void __launch_bounds__(128) k_main(const float* __restrict__ nf) {
    __shared__ ulonglong2 su3[NM3];     // 13056 B
    __shared__ ulonglong2 su2[NM2];     //  2176 B
    __shared__ ulonglong2 su1[Dd];      //   256 B
    int c = blockIdx.x, e = blockIdx.y, half = blockIdx.z;
    int t = threadIdx.x;
    int ec = e*Cc + c;
    const ulonglong2* G3 = reinterpret_cast<const ulonglong2*>(g_uw3s) + ec*NM3;
    const ulonglong2* G2 = reinterpret_cast<const ulonglong2*>(g_uw2s) + ec*NM2;
    const ulonglong2* G1 = reinterpret_cast<const ulonglong2*>(g_uw1s) + ec*Dd;
    for (int idx = t; idx < NM3; idx += 128) su3[idx] = G3[idx];
    for (int idx = t; idx < NM2; idx += 128) su2[idx] = G2[idx];
    if (t < Dd) su1[t] = G1[t];
    __syncthreads();
    int n = g_count[e];
    for (int base = half*128; base < n; base += 256) {
        int li = base + t;
        if (li >= n) continue;            // no barriers below: safe divergence
        int b = g_list[e*Bn + li];
        const float4* src = reinterpret_cast<const float4*>(nf + (b*Cc + c)*Dd);
        float4 v0 = src[0], v1 = src[1], v2 = src[2], v3 = src[3];
        float x[16] = {v0.x,v0.y,v0.z,v0.w, v1.x,v1.y,v1.z,v1.w,
                       v2.x,v2.y,v2.z,v2.w, v3.x,v3.y,v3.z,v3.w};
        u64 xd[16];                        // {x_i, x_i} packed
        #pragma unroll
        for (int i = 0; i < 16; i++) {
            unsigned xi = __float_as_uint(x[i]);
            asm("mov.b64 %0, {%1, %1};" : "=l"(xd[i]) : "r"(xi));
        }
        u64 acc01 = 0ull, acc23 = 0ull;    // {a0,a1}, {a2,a3}
        int m3 = 0, m2 = 0;
        #pragma unroll
        for (int i = 0; i < 16; i++) {
            ulonglong2 u1r = su1[i];
            FMA2(acc01, u1r.x, xd[i]);
            FMA2(acc23, u1r.y, xd[i]);
            #pragma unroll
            for (int j = i; j < 16; j++) {
                u64 xx2; MUL2(xx2, xd[i], xd[j]);      // {xi*xj, xi*xj}
                ulonglong2 u2r = su2[m2++];
                FMA2(acc01, u2r.x, xx2);
                FMA2(acc23, u2r.y, xx2);
                #pragma unroll
                for (int l = j; l < 16; l++) {
                    u64 mm2; MUL2(mm2, xx2, xd[l]);    // {xi*xj*xl, ...}
                    ulonglong2 u = su3[m3++];          // LDS.128 broadcast
                    FMA2(acc01, u.x, mm2);
                    FMA2(acc23, u.y, mm2);
                }
            }
        }
        unsigned r0, r1, r2, r3;
        asm("mov.b64 {%0,%1}, %2;" : "=r"(r0), "=r"(r1) : "l"(acc01));
        asm("mov.b64 {%0,%1}, %2;" : "=r"(r2), "=r"(r3) : "l"(acc23));
        g_Y[(0*Cc + c)*Bn + b] = __uint_as_float(r0);
        g_Y[(1*Cc + c)*Bn + b] = __uint_as_float(r1);
        g_Y[(2*Cc + c)*Bn + b] = __uint_as_float(r2);
        g_Y[(3*Cc + c)*Bn + b] = __uint_as_float(r3);
    }
}

// ---------------- final equivariant linear (channel mix) ----------------
__global__ void __launch_bounds__(256) k_linear(const float* __restrict__ wlin,
                                                float* __restrict__ out) {
    __shared__ float Ys[32][32];
    __shared__ float Ws[32][128];
    int o  = blockIdx.y;
    int b0 = blockIdx.x * 32;
    int set = (o == 0) ? 0 : 1;
    int t  = threadIdx.x;
    int tb = t & 31;          // node within tile
    int tg = t >> 5;          // 8 groups of 16 output channels
    const float scale = 0.08838834764831845f;    // 1/sqrt(128)
    float acc[16];
    #pragma unroll
    for (int q = 0; q < 16; q++) acc[q] = 0.f;
    for (int c0 = 0; c0 < Cc; c0 += 32) {
        __syncthreads();
        for (int idx = t; idx < 32*32; idx += 256) {
            int cc = idx >> 5, bb = idx & 31;
            Ys[cc][bb] = g_Y[(o*Cc + c0 + cc)*Bn + b0 + bb];
        }
        for (int idx = t; idx < 32*128; idx += 256) {
            int cc = idx >> 7, nn = idx & 127;
            Ws[cc][nn] = wlin[(set*Cc + c0 + cc)*Cc + nn] * scale;
        }
        __syncthreads();
        #pragma unroll
        for (int cc = 0; cc < 32; cc++) {
            float a = Ys[cc][tb];
            #pragma unroll
            for (int q = 0; q < 16; q++)
                acc[q] += a * Ws[cc][tg*16 + q];      // warp-uniform broadcast
        }
    }
    int b = b0 + tb;
    if (o == 0) {
        #pragma unroll
        for (int q = 0; q < 16; q++)
            out[b*512 + tg*16 + q] = acc[q];
    } else {
        int op = o - 1;
        #pragma unroll
        for (int q = 0; q < 16; q++)
            out[b*512 + 128 + (tg*16 + q)*3 + op] = acc[q];
    }
}

// ---------------- launch ----------------
extern "C" void kernel_launch(void* const* d_in, const int* in_sizes, int n_in,
                              void* d_out, int out_size) {
    const float* nf   = (const float*)d_in[0];
    const float* u3_0 = (const float*)d_in[1];
    const float* u3_1 = (const float*)d_in[2];
    const float* u2_0 = (const float*)d_in[3];
    const float* u2_1 = (const float*)d_in[4];
    const float* u1_0 = (const float*)d_in[5];
    const float* u1_1 = (const float*)d_in[6];
    const float* w3   = (const float*)d_in[7];
    const float* w2   = (const float*)d_in[8];
    const float* w1   = (const float*)d_in[9];
    const float* wl   = (const float*)d_in[10];
    const int*   sp   = (const int*)d_in[11];
    float* out = (float*)d_out;

    k_prep<<<69, 256>>>(sp, u3_0, u3_1, u2_0, u2_1);
    k_fold<<<F3_BLKS + F2_BLKS + F1_BLKS, 256>>>(w3, w2, u1_0, u1_1, w1);
    k_main<<<dim3(Cc, Ss, 2), 128>>>(nf);
    k_linear<<<dim3(Bn/32, 4), 256>>>(wl, out);
}

// round 3
// speedup vs baseline: 1.6250x; 1.0583x over previous
#include <cuda_runtime.h>

#define Bn 1024
#define Cc 128
#define Dd 16
#define Ss 4
#define NK3 23
#define NK2 5
#define NK1 2
#define NM3 816   // # monomials i<=j<=l, D=16 -> C(18,3)
#define NM2 136   // # pairs i<=j
#define OT 4      // total output irrep components: 1 (0e) + 3 (1o)

typedef unsigned long long u64;

// ---------------- scratch (device globals; no allocation allowed) ----------------
__device__ float  g_u3s[OT*NK3*NM3 + 64]; // symmetrized u3 basis, layout [o][k][m] (+pad)
__device__ float  g_u2s[OT*NK2*NM2];      // symmetrized u2 basis, layout [o][k][m]
__device__ float4 g_uw3s[Ss*Cc*NM3];      // per-(species,channel) weighted basis, float4 over o
__device__ float4 g_uw2s[Ss*Cc*NM2];
__device__ float4 g_uw1s[Ss*Cc*Dd];
__device__ float  g_Y[OT*Cc*Bn];          // y[o][c][p]  (p = species-compact position)
__device__ int    g_count[Ss];
__device__ int    g_list[Ss*Bn];
__device__ int    g_pb[Bn];               // compact position -> node index

// ---------------- fused prep: species sort/compact + symmetrize u3/u2 ----------------
__device__ __forceinline__ float u3at(const float* __restrict__ u3_0,
                                      const float* __restrict__ u3_1,
                                      int o, int a, int b, int c, int k) {
    if (o == 0) return u3_0[((a*Dd + b)*Dd + c)*NK3 + k];
    return u3_1[((((o-1)*Dd + a)*Dd + b)*Dd + c)*NK3 + k];
}

__global__ void k_prep(const int* __restrict__ sp,
                       const float* __restrict__ u3_0, const float* __restrict__ u3_1,
                       const float* __restrict__ u2_0, const float* __restrict__ u2_1) {
    int blk = blockIdx.x;
    int t = threadIdx.x;                 // 256 threads
    if (blk == 0) {
        // species counting-sort + compaction (single block so ordering is safe)
        if (t < Ss) g_count[t] = 0;
        __syncthreads();
        for (int b = t; b < Bn; b += 256) {
            int e = sp[b];
            int pos = atomicAdd(&g_count[e], 1);
            g_list[e*Bn + pos] = b;
        }
        __syncthreads();
        int off = 0;
        for (int e = 0; e < Ss; e++) {
            int n = g_count[e];
            for (int i = t; i < n; i += 256) g_pb[off + i] = g_list[e*Bn + i];
            off += n;
        }
    } else if (blk <= 64) {
        // symmetrize u3 -> g_u3s[o][k][m]
        int tid = (blk-1)*256 + t;       // 0..16383 = 4 * 4096
        int o = tid >> 12;
        int r = tid & 4095;
        int i = (r >> 8) & 15, j = (r >> 4) & 15, l = r & 15;
        if (i > j || j > l) return;
        int m = 0;
        for (int a = 0; a < i; a++) m += (Dd-a)*(Dd-a+1)/2;
        for (int b2 = i; b2 < j; b2++) m += (Dd-b2);
        m += l - j;
        int P[6][3] = {{i,j,l},{i,l,j},{j,i,l},{j,l,i},{l,i,j},{l,j,i}};
        bool use[6];
        #pragma unroll
        for (int p = 0; p < 6; p++) {
            use[p] = true;
            for (int q = 0; q < p; q++)
                if (P[q][0]==P[p][0] && P[q][1]==P[p][1] && P[q][2]==P[p][2]) { use[p] = false; break; }
        }
        for (int k = 0; k < NK3; k++) {
            float s = 0.f;
            #pragma unroll
            for (int p = 0; p < 6; p++)
                if (use[p]) s += u3at(u3_0, u3_1, o, P[p][0], P[p][1], P[p][2], k);
            g_u3s[(o*NK3 + k)*NM3 + m] = s;
        }
    } else {
        // symmetrize u2 -> g_u2s[o][k][m]
        int tid = (blk-65)*256 + t;      // 0..1023 = 4 * 256
        if (tid >= OT*256) return;
        int o = tid >> 8;
        int r = tid & 255;
        int i = (r >> 4) & 15, j = r & 15;
        if (i > j) return;
        int m = 0;
        for (int a = 0; a < i; a++) m += (Dd - a);
        m += j - i;
        for (int k = 0; k < NK2; k++) {
            float s;
            if (o == 0) {
                s = u2_0[(i*Dd + j)*NK2 + k];
                if (i != j) s += u2_0[(j*Dd + i)*NK2 + k];
            } else {
                s = u2_1[(((o-1)*Dd + i)*Dd + j)*NK2 + k];
                if (i != j) s += u2_1[(((o-1)*Dd + j)*Dd + i)*NK2 + k];
            }
            g_u2s[(o*NK2 + k)*NM2 + m] = s;
        }
    }
}

// ---------------- fused fold: species weights into bases ----------------
// fold3: smem-tiled. 104 CTAs = 4 species x 13 m-tiles(64) x 2 c-halves(64).
#define F3_BLKS 104
#define F2_BLKS (Ss*Cc*NM2/256)   // 272
#define F1_BLKS (Ss*Cc*Dd/256)    // 32

__global__ void __launch_bounds__(256) k_fold(
        const float* __restrict__ w3, const float* __restrict__ w2,
        const float* __restrict__ u1_0, const float* __restrict__ u1_1,
        const float* __restrict__ w1) {
    int blk = blockIdx.x;
    int t = threadIdx.x;
    if (blk < F3_BLKS) {
        __shared__ float su[OT][NK3][64];   // 23.5 KB
        __shared__ float sw[2][NK3][64];    // 11.8 KB
        int e  = blk / 26;
        int r  = blk % 26;
        int m0 = (r >> 1) * 64;
        int c0 = (r & 1) * 64;
        for (int idx = t; idx < OT*NK3*64; idx += 256) {
            int m = idx & 63; int ok = idx >> 6; int k = ok % NK3; int o = ok / NK3;
            su[o][k][m] = g_u3s[(o*NK3 + k)*NM3 + m0 + m];   // may over-read into pad
        }
        for (int idx = t; idx < 2*NK3*64; idx += 256) {
            int cw = idx & 63; int sk = idx >> 6; int k = sk % NK3; int s = sk / NK3;
            sw[s][k][cw] = w3[((s*Ss + e)*NK3 + k)*Cc + c0 + cw];
        }
        __syncthreads();
        int m = t & 63;
        int cq = t >> 6;
        bool valid = (m0 + m) < NM3;
        #pragma unroll
        for (int ci = 0; ci < 4; ci++) {
            int cl = cq*16 + ci*4;
            float s00=0,s01=0,s02=0,s03=0, s10=0,s11=0,s12=0,s13=0;
            float s20=0,s21=0,s22=0,s23=0, s30=0,s31=0,s32=0,s33=0;
            #pragma unroll
            for (int k = 0; k < NK3; k++) {
                float u0 = su[0][k][m], u1 = su[1][k][m];
                float u2 = su[2][k][m], u3 = su[3][k][m];
                float4 wa = *reinterpret_cast<float4*>(&sw[0][k][cl]);
                float4 wb = *reinterpret_cast<float4*>(&sw[1][k][cl]);
                s00 += u0*wa.x; s01 += u1*wb.x; s02 += u2*wb.x; s03 += u3*wb.x;
                s10 += u0*wa.y; s11 += u1*wb.y; s12 += u2*wb.y; s13 += u3*wb.y;
                s20 += u0*wa.z; s21 += u1*wb.z; s22 += u2*wb.z; s23 += u3*wb.z;
                s30 += u0*wa.w; s31 += u1*wb.w; s32 += u2*wb.w; s33 += u3*wb.w;
            }
            if (valid) {
                int mm = m0 + m;
                g_uw3s[(e*Cc + c0 + cl + 0)*NM3 + mm] = make_float4(s00,s01,s02,s03);
                g_uw3s[(e*Cc + c0 + cl + 1)*NM3 + mm] = make_float4(s10,s11,s12,s13);
                g_uw3s[(e*Cc + c0 + cl + 2)*NM3 + mm] = make_float4(s20,s21,s22,s23);
                g_uw3s[(e*Cc + c0 + cl + 3)*NM3 + mm] = make_float4(s30,s31,s32,s33);
            }
        }
    } else if (blk < F3_BLKS + F2_BLKS) {
        int tid = (blk - F3_BLKS)*256 + t;
        int m = tid % NM2; int ec = tid / NM2;
        int c = ec % Cc;   int e  = ec / Cc;
        const float* w0  = w2 + ((0*Ss + e)*NK2)*Cc + c;
        const float* w1v = w2 + ((1*Ss + e)*NK2)*Cc + c;
        float s0=0.f, s1=0.f, s2=0.f, s3=0.f;
        #pragma unroll
        for (int k = 0; k < NK2; k++) {
            float a = __ldg(w0 + k*Cc), b = __ldg(w1v + k*Cc);
            s0 += g_u2s[(0*NK2 + k)*NM2 + m]*a;
            s1 += g_u2s[(1*NK2 + k)*NM2 + m]*b;
            s2 += g_u2s[(2*NK2 + k)*NM2 + m]*b;
            s3 += g_u2s[(3*NK2 + k)*NM2 + m]*b;
        }
        g_uw2s[tid] = make_float4(s0,s1,s2,s3);
    } else {
        int tid = (blk - F3_BLKS - F2_BLKS)*256 + t;
        int i = tid % Dd; int ec = tid / Dd;
        int c = ec % Cc;  int e  = ec / Cc;
        float s[OT];
        #pragma unroll
        for (int o = 0; o < OT; o++) {
            int set = (o == 0) ? 0 : 1;
            float acc = 0.f;
            #pragma unroll
            for (int k = 0; k < NK1; k++) {
                float uv = (o == 0) ? u1_0[i*NK1 + k]
                                    : u1_1[(((o-1)*Dd) + i)*NK1 + k];
                acc += uv * w1[((set*Ss + e)*NK1 + k)*Cc + c];
            }
            s[o] = acc;
        }
        g_uw1s[tid] = make_float4(s[0], s[1], s[2], s[3]);
    }
}

// ---------------- main symmetric-contraction kernel (packed f32x2) ----------------
#define FMA2(acc, a, b) asm("fma.rn.f32x2 %0, %1, %2, %0;" : "+l"(acc) : "l"(a), "l"(b))
#define MUL2(d, a, b)   asm("mul.rn.f32x2 %0, %1, %2;" : "=l"(d) : "l"(a), "l"(b))

__global__ void __launch_bounds__(128) k_main(const float* __restrict__ nf) {
    __shared__ ulonglong2 su3[NM3];     // 13056 B
    __shared__ ulonglong2 su2[NM2];     //  2176 B
    __shared__ ulonglong2 su1[Dd];      //   256 B
    int c = blockIdx.x, e = blockIdx.y, half = blockIdx.z;
    int t = threadIdx.x;
    int ec = e*Cc + c;
    const ulonglong2* G3 = reinterpret_cast<const ulonglong2*>(g_uw3s) + ec*NM3;
    const ulonglong2* G2 = reinterpret_cast<const ulonglong2*>(g_uw2s) + ec*NM2;
    const ulonglong2* G1 = reinterpret_cast<const ulonglong2*>(g_uw1s) + ec*Dd;
    for (int idx = t; idx < NM3; idx += 128) su3[idx] = G3[idx];
    for (int idx = t; idx < NM2; idx += 128) su2[idx] = G2[idx];
    if (t < Dd) su1[t] = G1[t];
    __syncthreads();
    int n = g_count[e];
    int off = 0;
    for (int q = 0; q < Ss; q++) if (q < e) off += g_count[q];
    for (int base = half*128; base < n; base += 256) {
        int li = base + t;
        if (li >= n) continue;            // no barriers below: safe divergence
        int p = off + li;
        int b = g_pb[p];
        const float4* src = reinterpret_cast<const float4*>(nf + (b*Cc + c)*Dd);
        float4 v0 = src[0], v1 = src[1], v2 = src[2], v3 = src[3];
        float x[16] = {v0.x,v0.y,v0.z,v0.w, v1.x,v1.y,v1.z,v1.w,
                       v2.x,v2.y,v2.z,v2.w, v3.x,v3.y,v3.z,v3.w};
        u64 xd[16];                        // {x_i, x_i} packed
        #pragma unroll
        for (int i = 0; i < 16; i++) {
            unsigned xi = __float_as_uint(x[i]);
            asm("mov.b64 %0, {%1, %1};" : "=l"(xd[i]) : "r"(xi));
        }
        u64 acc01 = 0ull, acc23 = 0ull;    // {a0,a1}, {a2,a3}
        int m3 = 0, m2 = 0;
        #pragma unroll
        for (int i = 0; i < 16; i++) {
            ulonglong2 u1r = su1[i];
            FMA2(acc01, u1r.x, xd[i]);
            FMA2(acc23, u1r.y, xd[i]);
            #pragma unroll
            for (int j = i; j < 16; j++) {
                u64 xx2; MUL2(xx2, xd[i], xd[j]);      // {xi*xj, xi*xj}
                ulonglong2 u2r = su2[m2++];
                FMA2(acc01, u2r.x, xx2);
                FMA2(acc23, u2r.y, xx2);
                #pragma unroll
                for (int l = j; l < 16; l++) {
                    u64 mm2; MUL2(mm2, xx2, xd[l]);    // {xi*xj*xl, ...}
                    ulonglong2 u = su3[m3++];          // LDS.128 broadcast
                    FMA2(acc01, u.x, mm2);
                    FMA2(acc23, u.y, mm2);
                }
            }
        }
        unsigned r0, r1, r2, r3;
        asm("mov.b64 {%0,%1}, %2;" : "=r"(r0), "=r"(r1) : "l"(acc01));
        asm("mov.b64 {%0,%1}, %2;" : "=r"(r2), "=r"(r3) : "l"(acc23));
        g_Y[(0*Cc + c)*Bn + p] = __uint_as_float(r0);   // coalesced: p = off+base+t
        g_Y[(1*Cc + c)*Bn + p] = __uint_as_float(r1);
        g_Y[(2*Cc + c)*Bn + p] = __uint_as_float(r2);
        g_Y[(3*Cc + c)*Bn + p] = __uint_as_float(r3);
    }
}

// ---------------- final equivariant linear (channel mix) ----------------
// Grid (64 p-tiles, 4 o). CTA: 16 rows x 128 cols, K-chunks of 32.
// Thread: 2 rows x 4 cols register tile -> 1 LDS.64 + 1 LDS.128 + 8 FMA per cc.
__global__ void __launch_bounds__(256) k_linear(const float* __restrict__ wlin,
                                                float* __restrict__ out) {
    __shared__ float Ys[32][16];
    __shared__ float Ws[32][128];
    int o  = blockIdx.y;
    int p0 = blockIdx.x * 16;
    int set = (o == 0) ? 0 : 1;
    int t  = threadIdx.x;
    int pq = t & 7;           // row-slot (2 rows each)
    int nq = t >> 3;          // col-slot (4 cols each)
    const float scale = 0.08838834764831845f;    // 1/sqrt(128)
    float a00=0,a01=0,a02=0,a03=0, a10=0,a11=0,a12=0,a13=0;
    for (int c0 = 0; c0 < Cc; c0 += 32) {
        __syncthreads();
        for (int idx = t; idx < 32*16; idx += 256) {
            int cc = idx >> 4, pp = idx & 15;
            Ys[cc][pp] = g_Y[(o*Cc + c0 + cc)*Bn + p0 + pp];
        }
        for (int idx = t; idx < 32*128; idx += 256) {
            int cc = idx >> 7, nn = idx & 127;
            Ws[cc][nn] = wlin[(set*Cc + c0 + cc)*Cc + nn] * scale;
        }
        __syncthreads();
        #pragma unroll
        for (int cc = 0; cc < 32; cc++) {
            float2 y = *reinterpret_cast<float2*>(&Ys[cc][pq*2]);
            float4 w = *reinterpret_cast<float4*>(&Ws[cc][nq*4]);
            a00 += y.x*w.x; a01 += y.x*w.y; a02 += y.x*w.z; a03 += y.x*w.w;
            a10 += y.y*w.x; a11 += y.y*w.y; a12 += y.y*w.z; a13 += y.y*w.w;
        }
    }
    int p_a = p0 + pq*2;
    int b_a = g_pb[p_a];
    int b_b = g_pb[p_a + 1];
    if (o == 0) {
        *reinterpret_cast<float4*>(&out[b_a*512 + nq*4]) = make_float4(a00,a01,a02,a03);
        *reinterpret_cast<float4*>(&out[b_b*512 + nq*4]) = make_float4(a10,a11,a12,a13);
    } else {
        int op = o - 1;
        out[b_a*512 + 128 + (nq*4 + 0)*3 + op] = a00;
        out[b_a*512 + 128 + (nq*4 + 1)*3 + op] = a01;
        out[b_a*512 + 128 + (nq*4 + 2)*3 + op] = a02;
        out[b_a*512 + 128 + (nq*4 + 3)*3 + op] = a03;
        out[b_b*512 + 128 + (nq*4 + 0)*3 + op] = a10;
        out[b_b*512 + 128 + (nq*4 + 1)*3 + op] = a11;
        out[b_b*512 + 128 + (nq*4 + 2)*3 + op] = a12;
        out[b_b*512 + 128 + (nq*4 + 3)*3 + op] = a13;
    }
}

// ---------------- launch ----------------
extern "C" void kernel_launch(void* const* d_in, const int* in_sizes, int n_in,
                              void* d_out, int out_size) {
    const float* nf   = (const float*)d_in[0];
    const float* u3_0 = (const float*)d_in[1];
    const float* u3_1 = (const float*)d_in[2];
    const float* u2_0 = (const float*)d_in[3];
    const float* u2_1 = (const float*)d_in[4];
    const float* u1_0 = (const float*)d_in[5];
    const float* u1_1 = (const float*)d_in[6];
    const float* w3   = (const float*)d_in[7];
    const float* w2   = (const float*)d_in[8];
    const float* w1   = (const float*)d_in[9];
    const float* wl   = (const float*)d_in[10];
    const int*   sp   = (const int*)d_in[11];
    float* out = (float*)d_out;

    k_prep<<<69, 256>>>(sp, u3_0, u3_1, u2_0, u2_1);
    k_fold<<<F3_BLKS + F2_BLKS + F1_BLKS, 256>>>(w3, w2, u1_0, u1_1, w1);
    k_main<<<dim3(Cc, Ss, 2), 128>>>(nf);
    k_linear<<<dim3(Bn/16, 4), 256>>>(wl, out);
}

// round 4
// speedup vs baseline: 1.8200x; 1.1200x over previous
#include <cuda_runtime.h>

#define Bn 1024
#define Cc 128
#define Dd 16
#define Ss 4
#define NK3 23
#define NK2 5
#define NK1 2
#define NM3 816   // # monomials i<=j<=l, D=16 -> C(18,3)
#define NM2 136   // # pairs i<=j
#define OT 4      // total output irrep components: 1 (0e) + 3 (1o)

typedef unsigned long long u64;

// ---------------- scratch (device globals; no allocation allowed) ----------------
__device__ float  g_u3s[OT*NK3*NM3 + 64]; // symmetrized u3 basis, layout [o][k][m] (+pad)
__device__ float  g_u2s[OT*NK2*NM2];      // symmetrized u2 basis, layout [o][k][m]
__device__ float4 g_uw3s[Ss*Cc*NM3];      // per-(species,channel) weighted basis, float4 over o
__device__ float4 g_uw2s[Ss*Cc*NM2];
__device__ float4 g_uw1s[Ss*Cc*Dd];
__device__ float  g_Y[OT*Cc*Bn];          // y[o][c][p]  (p = species-compact position)
__device__ int    g_count[Ss];
__device__ int    g_list[Ss*Bn];
__device__ int    g_pb[Bn];               // compact position -> node index

// ---------------- fused prep: species sort/compact + symmetrize u3/u2 ----------------
__device__ __forceinline__ float u3at(const float* __restrict__ u3_0,
                                      const float* __restrict__ u3_1,
                                      int o, int a, int b, int c, int k) {
    if (o == 0) return u3_0[((a*Dd + b)*Dd + c)*NK3 + k];
    return u3_1[((((o-1)*Dd + a)*Dd + b)*Dd + c)*NK3 + k];
}

__global__ void k_prep(const int* __restrict__ sp,
                       const float* __restrict__ u3_0, const float* __restrict__ u3_1,
                       const float* __restrict__ u2_0, const float* __restrict__ u2_1) {
    int blk = blockIdx.x;
    int t = threadIdx.x;                 // 256 threads
    if (blk == 0) {
        // species counting-sort + compaction (single block so ordering is safe)
        if (t < Ss) g_count[t] = 0;
        __syncthreads();
        for (int b = t; b < Bn; b += 256) {
            int e = sp[b];
            int pos = atomicAdd(&g_count[e], 1);
            g_list[e*Bn + pos] = b;
        }
        __syncthreads();
        int off = 0;
        for (int e = 0; e < Ss; e++) {
            int n = g_count[e];
            for (int i = t; i < n; i += 256) g_pb[off + i] = g_list[e*Bn + i];
            off += n;
        }
    } else if (blk <= 64) {
        // symmetrize u3 -> g_u3s[o][k][m]
        int tid = (blk-1)*256 + t;       // 0..16383 = 4 * 4096
        int o = tid >> 12;
        int r = tid & 4095;
        int i = (r >> 8) & 15, j = (r >> 4) & 15, l = r & 15;
        if (i > j || j > l) return;
        int m = 0;
        for (int a = 0; a < i; a++) m += (Dd-a)*(Dd-a+1)/2;
        for (int b2 = i; b2 < j; b2++) m += (Dd-b2);
        m += l - j;
        int P[6][3] = {{i,j,l},{i,l,j},{j,i,l},{j,l,i},{l,i,j},{l,j,i}};
        bool use[6];
        #pragma unroll
        for (int p = 0; p < 6; p++) {
            use[p] = true;
            for (int q = 0; q < p; q++)
                if (P[q][0]==P[p][0] && P[q][1]==P[p][1] && P[q][2]==P[p][2]) { use[p] = false; break; }
        }
        for (int k = 0; k < NK3; k++) {
            float s = 0.f;
            #pragma unroll
            for (int p = 0; p < 6; p++)
                if (use[p]) s += u3at(u3_0, u3_1, o, P[p][0], P[p][1], P[p][2], k);
            g_u3s[(o*NK3 + k)*NM3 + m] = s;
        }
    } else {
        // symmetrize u2 -> g_u2s[o][k][m]
        int tid = (blk-65)*256 + t;      // 0..1023 = 4 * 256
        if (tid >= OT*256) return;
        int o = tid >> 8;
        int r = tid & 255;
        int i = (r >> 4) & 15, j = r & 15;
        if (i > j) return;
        int m = 0;
        for (int a = 0; a < i; a++) m += (Dd - a);
        m += j - i;
        for (int k = 0; k < NK2; k++) {
            float s;
            if (o == 0) {
                s = u2_0[(i*Dd + j)*NK2 + k];
                if (i != j) s += u2_0[(j*Dd + i)*NK2 + k];
            } else {
                s = u2_1[(((o-1)*Dd + i)*Dd + j)*NK2 + k];
                if (i != j) s += u2_1[(((o-1)*Dd + j)*Dd + i)*NK2 + k];
            }
            g_u2s[(o*NK2 + k)*NM2 + m] = s;
        }
    }
}

// ---------------- fused fold: species weights into bases ----------------
// fold3: smem-tiled. 104 CTAs = 4 species x 13 m-tiles(64) x 2 c-halves(64).
#define F3_BLKS 104
#define F2_BLKS (Ss*Cc*NM2/256)   // 272
#define F1_BLKS (Ss*Cc*Dd/256)    // 32

__global__ void __launch_bounds__(256) k_fold(
        const float* __restrict__ w3, const float* __restrict__ w2,
        const float* __restrict__ u1_0, const float* __restrict__ u1_1,
        const float* __restrict__ w1) {
    int blk = blockIdx.x;
    int t = threadIdx.x;
    if (blk < F3_BLKS) {
        __shared__ float su[OT][NK3][64];   // 23.5 KB
        __shared__ float sw[2][NK3][64];    // 11.8 KB
        int e  = blk / 26;
        int r  = blk % 26;
        int m0 = (r >> 1) * 64;
        int c0 = (r & 1) * 64;
        for (int idx = t; idx < OT*NK3*64; idx += 256) {
            int m = idx & 63; int ok = idx >> 6; int k = ok % NK3; int o = ok / NK3;
            su[o][k][m] = g_u3s[(o*NK3 + k)*NM3 + m0 + m];   // may over-read into pad
        }
        for (int idx = t; idx < 2*NK3*64; idx += 256) {
            int cw = idx & 63; int sk = idx >> 6; int k = sk % NK3; int s = sk / NK3;
            sw[s][k][cw] = w3[((s*Ss + e)*NK3 + k)*Cc + c0 + cw];
        }
        __syncthreads();
        int m = t & 63;
        int cq = t >> 6;
        bool valid = (m0 + m) < NM3;
        #pragma unroll
        for (int ci = 0; ci < 4; ci++) {
            int cl = cq*16 + ci*4;
            float s00=0,s01=0,s02=0,s03=0, s10=0,s11=0,s12=0,s13=0;
            float s20=0,s21=0,s22=0,s23=0, s30=0,s31=0,s32=0,s33=0;
            #pragma unroll
            for (int k = 0; k < NK3; k++) {
                float u0 = su[0][k][m], u1 = su[1][k][m];
                float u2 = su[2][k][m], u3 = su[3][k][m];
                float4 wa = *reinterpret_cast<float4*>(&sw[0][k][cl]);
                float4 wb = *reinterpret_cast<float4*>(&sw[1][k][cl]);
                s00 += u0*wa.x; s01 += u1*wb.x; s02 += u2*wb.x; s03 += u3*wb.x;
                s10 += u0*wa.y; s11 += u1*wb.y; s12 += u2*wb.y; s13 += u3*wb.y;
                s20 += u0*wa.z; s21 += u1*wb.z; s22 += u2*wb.z; s23 += u3*wb.z;
                s30 += u0*wa.w; s31 += u1*wb.w; s32 += u2*wb.w; s33 += u3*wb.w;
            }
            if (valid) {
                int mm = m0 + m;
                g_uw3s[(e*Cc + c0 + cl + 0)*NM3 + mm] = make_float4(s00,s01,s02,s03);
                g_uw3s[(e*Cc + c0 + cl + 1)*NM3 + mm] = make_float4(s10,s11,s12,s13);
                g_uw3s[(e*Cc + c0 + cl + 2)*NM3 + mm] = make_float4(s20,s21,s22,s23);
                g_uw3s[(e*Cc + c0 + cl + 3)*NM3 + mm] = make_float4(s30,s31,s32,s33);
            }
        }
    } else if (blk < F3_BLKS + F2_BLKS) {
        int tid = (blk - F3_BLKS)*256 + t;
        int m = tid % NM2; int ec = tid / NM2;
        int c = ec % Cc;   int e  = ec / Cc;
        const float* w0  = w2 + ((0*Ss + e)*NK2)*Cc + c;
        const float* w1v = w2 + ((1*Ss + e)*NK2)*Cc + c;
        float s0=0.f, s1=0.f, s2=0.f, s3=0.f;
        #pragma unroll
        for (int k = 0; k < NK2; k++) {
            float a = __ldg(w0 + k*Cc), b = __ldg(w1v + k*Cc);
            s0 += g_u2s[(0*NK2 + k)*NM2 + m]*a;
            s1 += g_u2s[(1*NK2 + k)*NM2 + m]*b;
            s2 += g_u2s[(2*NK2 + k)*NM2 + m]*b;
            s3 += g_u2s[(3*NK2 + k)*NM2 + m]*b;
        }
        g_uw2s[tid] = make_float4(s0,s1,s2,s3);
    } else {
        int tid = (blk - F3_BLKS - F2_BLKS)*256 + t;
        int i = tid % Dd; int ec = tid / Dd;
        int c = ec % Cc;  int e  = ec / Cc;
        float s[OT];
        #pragma unroll
        for (int o = 0; o < OT; o++) {
            int set = (o == 0) ? 0 : 1;
            float acc = 0.f;
            #pragma unroll
            for (int k = 0; k < NK1; k++) {
                float uv = (o == 0) ? u1_0[i*NK1 + k]
                                    : u1_1[(((o-1)*Dd) + i)*NK1 + k];
                acc += uv * w1[((set*Ss + e)*NK1 + k)*Cc + c];
            }
            s[o] = acc;
        }
        g_uw1s[tid] = make_float4(s[0], s[1], s[2], s[3]);
    }
}

// ---------------- main symmetric-contraction kernel (packed f32x2, dot-trick) ----------------
#define FMA2(acc, a, b) asm("fma.rn.f32x2 %0, %1, %2, %0;" : "+l"(acc) : "l"(a), "l"(b))
#define MUL2(d, a, b)   asm("mul.rn.f32x2 %0, %1, %2;" : "=l"(d) : "l"(a), "l"(b))

__global__ void __launch_bounds__(128) k_main(const float* __restrict__ nf) {
    __shared__ ulonglong2 su3[NM3];     // 13056 B
    __shared__ ulonglong2 su2[NM2];     //  2176 B
    __shared__ ulonglong2 su1[Dd];      //   256 B
    int c = blockIdx.x, e = blockIdx.y, half = blockIdx.z;
    int t = threadIdx.x;
    int ec = e*Cc + c;
    const ulonglong2* G3 = reinterpret_cast<const ulonglong2*>(g_uw3s) + ec*NM3;
    const ulonglong2* G2 = reinterpret_cast<const ulonglong2*>(g_uw2s) + ec*NM2;
    const ulonglong2* G1 = reinterpret_cast<const ulonglong2*>(g_uw1s) + ec*Dd;
    for (int idx = t; idx < NM3; idx += 128) su3[idx] = G3[idx];
    for (int idx = t; idx < NM2; idx += 128) su2[idx] = G2[idx];
    if (t < Dd) su1[t] = G1[t];
    __syncthreads();
    int n = g_count[e];
    int off = 0;
    for (int q = 0; q < Ss; q++) if (q < e) off += g_count[q];
    for (int base = half*128; base < n; base += 256) {
        int li = base + t;
        if (li >= n) continue;            // no barriers below: safe divergence
        int p = off + li;
        int b = g_pb[p];
        const float4* src = reinterpret_cast<const float4*>(nf + (b*Cc + c)*Dd);
        float4 v0 = src[0], v1 = src[1], v2 = src[2], v3 = src[3];
        float x[16] = {v0.x,v0.y,v0.z,v0.w, v1.x,v1.y,v1.z,v1.w,
                       v2.x,v2.y,v2.z,v2.w, v3.x,v3.y,v3.z,v3.w};
        u64 xd[16];                        // {x_i, x_i} packed
        #pragma unroll
        for (int i = 0; i < 16; i++) {
            unsigned xi = __float_as_uint(x[i]);
            asm("mov.b64 %0, {%1, %1};" : "=l"(xd[i]) : "r"(xi));
        }
        u64 acc01 = 0ull, acc23 = 0ull;    // {a0,a1}, {a2,a3}
        int m3 = 0, m2 = 0;
        #pragma unroll
        for (int i = 0; i < 16; i++) {
            ulonglong2 u1r = su1[i];
            FMA2(acc01, u1r.x, xd[i]);
            FMA2(acc23, u1r.y, xd[i]);
            #pragma unroll
            for (int j = i; j < 16; j++) {
                u64 xx2; MUL2(xx2, xd[i], xd[j]);      // {xi*xj, xi*xj}
                ulonglong2 u2r = su2[m2++];
                u64 d01 = u2r.x, d23 = u2r.y;          // dot = u2 + sum_l u3*x_l
                #pragma unroll
                for (int l = j; l < 16; l++) {
                    ulonglong2 u = su3[m3++];          // LDS.128 broadcast
                    FMA2(d01, u.x, xd[l]);
                    FMA2(d23, u.y, xd[l]);
                }
                FMA2(acc01, xx2, d01);                 // acc += xx * dot
                FMA2(acc23, xx2, d23);
            }
        }
        unsigned r0, r1, r2, r3;
        asm("mov.b64 {%0,%1}, %2;" : "=r"(r0), "=r"(r1) : "l"(acc01));
        asm("mov.b64 {%0,%1}, %2;" : "=r"(r2), "=r"(r3) : "l"(acc23));
        g_Y[(0*Cc + c)*Bn + p] = __uint_as_float(r0);   // coalesced: p = off+base+t
        g_Y[(1*Cc + c)*Bn + p] = __uint_as_float(r1);
        g_Y[(2*Cc + c)*Bn + p] = __uint_as_float(r2);
        g_Y[(3*Cc + c)*Bn + p] = __uint_as_float(r3);
    }
}

// ---------------- final equivariant linear (channel mix) ----------------
// Whole K=128 resident in dynamic smem; ONE barrier; barrier-free unrolled mainloop.
// Grid (64 p-tiles of 16, 4 o). Thread: 2 rows x 4 cols.
#define LIN_SMEM (Cc*Cc*4 + Cc*16*4)   // Ws 64KB + Ys 8KB = 73728 B
__global__ void __launch_bounds__(256) k_linear(const float* __restrict__ wlin,
                                                float* __restrict__ out) {
    extern __shared__ float sm[];
    float* Ws = sm;              // [128][128]
    float* Ys = sm + Cc*Cc;      // [128][16]
    int o  = blockIdx.y;
    int p0 = blockIdx.x * 16;
    int set = (o == 0) ? 0 : 1;
    int t  = threadIdx.x;
    const float4* wsrc = reinterpret_cast<const float4*>(wlin + set*Cc*Cc);
    float4* wdst = reinterpret_cast<float4*>(Ws);
    #pragma unroll
    for (int idx = t; idx < Cc*Cc/4; idx += 256) wdst[idx] = wsrc[idx];
    #pragma unroll
    for (int idx = t; idx < Cc*16; idx += 256) {
        int cc = idx >> 4, pp = idx & 15;
        Ys[cc*16 + pp] = g_Y[(o*Cc + cc)*Bn + p0 + pp];
    }
    __syncthreads();
    int pq = t & 7;           // row-slot (2 rows each)
    int nq = t >> 3;          // col-slot (4 cols each)
    float a00=0,a01=0,a02=0,a03=0, a10=0,a11=0,a12=0,a13=0;
    #pragma unroll 16
    for (int cc = 0; cc < Cc; cc++) {
        float2 y = *reinterpret_cast<float2*>(&Ys[cc*16 + pq*2]);
        float4 w = *reinterpret_cast<float4*>(&Ws[cc*Cc + nq*4]);
        a00 += y.x*w.x; a01 += y.x*w.y; a02 += y.x*w.z; a03 += y.x*w.w;
        a10 += y.y*w.x; a11 += y.y*w.y; a12 += y.y*w.z; a13 += y.y*w.w;
    }
    const float scale = 0.08838834764831845f;    // 1/sqrt(128)
    a00*=scale; a01*=scale; a02*=scale; a03*=scale;
    a10*=scale; a11*=scale; a12*=scale; a13*=scale;
    int p_a = p0 + pq*2;
    int b_a = g_pb[p_a];
    int b_b = g_pb[p_a + 1];
    if (o == 0) {
        *reinterpret_cast<float4*>(&out[b_a*512 + nq*4]) = make_float4(a00,a01,a02,a03);
        *reinterpret_cast<float4*>(&out[b_b*512 + nq*4]) = make_float4(a10,a11,a12,a13);
    } else {
        int op = o - 1;
        out[b_a*512 + 128 + (nq*4 + 0)*3 + op] = a00;
        out[b_a*512 + 128 + (nq*4 + 1)*3 + op] = a01;
        out[b_a*512 + 128 + (nq*4 + 2)*3 + op] = a02;
        out[b_a*512 + 128 + (nq*4 + 3)*3 + op] = a03;
        out[b_b*512 + 128 + (nq*4 + 0)*3 + op] = a10;
        out[b_b*512 + 128 + (nq*4 + 1)*3 + op] = a11;
        out[b_b*512 + 128 + (nq*4 + 2)*3 + op] = a12;
        out[b_b*512 + 128 + (nq*4 + 3)*3 + op] = a13;
    }
}

// ---------------- launch ----------------
extern "C" void kernel_launch(void* const* d_in, const int* in_sizes, int n_in,
                              void* d_out, int out_size) {
    const float* nf   = (const float*)d_in[0];
    const float* u3_0 = (const float*)d_in[1];
    const float* u3_1 = (const float*)d_in[2];
    const float* u2_0 = (const float*)d_in[3];
    const float* u2_1 = (const float*)d_in[4];
    const float* u1_0 = (const float*)d_in[5];
    const float* u1_1 = (const float*)d_in[6];
    const float* w3   = (const float*)d_in[7];
    const float* w2   = (const float*)d_in[8];
    const float* w1   = (const float*)d_in[9];
    const float* wl   = (const float*)d_in[10];
    const int*   sp   = (const int*)d_in[11];
    float* out = (float*)d_out;

    static int init_done = 0;
    if (!init_done) {
        cudaFuncSetAttribute(k_linear, cudaFuncAttributeMaxDynamicSharedMemorySize, LIN_SMEM);
        init_done = 1;
    }

    k_prep<<<69, 256>>>(sp, u3_0, u3_1, u2_0, u2_1);
    k_fold<<<F3_BLKS + F2_BLKS + F1_BLKS, 256>>>(w3, w2, u1_0, u1_1, w1);
    k_main<<<dim3(Cc, Ss, 2), 128>>>(nf);
    k_linear<<<dim3(Bn/16, 4), 256, LIN_SMEM>>>(wl, out);
}

// round 5
// speedup vs baseline: 1.9646x; 1.0794x over previous
#include <cuda_runtime.h>

#define Bn 1024
#define Cc 128
#define Dd 16
#define Ss 4
#define NK3 23
#define NK2 5
#define NK1 2
#define NM3 816   // # monomials, ordered by (j, i, l): m = off3[j] + i*(16-j) + (l-j)
#define NM2 136   // # pairs, ordered by (j, i): m = j(j+1)/2 + i
#define OT 4      // total output irrep components: 1 (0e) + 3 (1o)

typedef unsigned long long u64;

// ---------------- scratch (device globals; no allocation allowed) ----------------
__device__ float  g_u3s[OT*NM3*NK3 + 512]; // symmetrized u3, layout [o][m][k] (+pad for tile over-read)
__device__ float  g_u2s[OT*NK2*NM2];       // symmetrized u2, layout [o][k][m]
__device__ float4 g_uw3s[Ss*Cc*NM3];       // per-(species,channel) weighted basis, float4 over o
__device__ float4 g_uw2s[Ss*Cc*NM2];
__device__ float4 g_uw1s[Ss*Cc*Dd];
__device__ float  g_Y[OT*Cc*Bn];           // y[o][c][p]  (p = species-compact position)
__device__ int    g_count[Ss];
__device__ int    g_list[Ss*Bn];
__device__ int    g_pb[Bn];                // compact position -> node index

// ---------------- fused prep: species sort/compact + symmetrize u3/u2 ----------------
__device__ __forceinline__ float u3at(const float* __restrict__ u3_0,
                                      const float* __restrict__ u3_1,
                                      int o, int a, int b, int c, int k) {
    if (o == 0) return u3_0[((a*Dd + b)*Dd + c)*NK3 + k];
    return u3_1[((((o-1)*Dd + a)*Dd + b)*Dd + c)*NK3 + k];
}

// prep grid: blk0 = sort; blk 1..294 = sym3 (thread per (o,m,k), coalesced); blk 295..298 = sym2
#define SYM3_BLKS 294
__global__ void k_prep(const int* __restrict__ sp,
                       const float* __restrict__ u3_0, const float* __restrict__ u3_1,
                       const float* __restrict__ u2_0, const float* __restrict__ u2_1) {
    int blk = blockIdx.x;
    int t = threadIdx.x;                 // 256 threads
    if (blk == 0) {
        // species counting-sort + compaction (single block so ordering is safe)
        if (t < Ss) g_count[t] = 0;
        __syncthreads();
        for (int b = t; b < Bn; b += 256) {
            int e = sp[b];
            int pos = atomicAdd(&g_count[e], 1);
            g_list[e*Bn + pos] = b;
        }
        __syncthreads();
        int off = 0;
        for (int e = 0; e < Ss; e++) {
            int n = g_count[e];
            for (int i = t; i < n; i += 256) g_pb[off + i] = g_list[e*Bn + i];
            off += n;
        }
    } else if (blk <= SYM3_BLKS) {
        // symmetrize u3 -> g_u3s[o][m][k], thread per (o,m,k)
        int tid = (blk-1)*256 + t;
        if (tid >= OT*NM3*NK3) return;
        int k  = tid % NK3;
        int om = tid / NK3;
        int m  = om % NM3;
        int o  = om / NM3;
        // decode m -> (i,j,l) in (j,i,l) ordering
        const int off3[17] = {0,16,46,88,140,200,266,336,408,480,550,616,676,728,770,800,816};
        int j = 0;
        #pragma unroll
        for (int q = 1; q < 16; q++) if (m >= off3[q]) j = q;
        int r = m - off3[j];
        int w = 16 - j;
        int i = r / w;
        int l = j + r % w;
        int P[6][3] = {{i,j,l},{i,l,j},{j,i,l},{j,l,i},{l,i,j},{l,j,i}};
        float s = 0.f;
        #pragma unroll
        for (int p = 0; p < 6; p++) {
            bool dup = false;
            for (int q = 0; q < p; q++)
                if (P[q][0]==P[p][0] && P[q][1]==P[p][1] && P[q][2]==P[p][2]) { dup = true; break; }
            if (!dup) s += u3at(u3_0, u3_1, o, P[p][0], P[p][1], P[p][2], k);
        }
        g_u3s[(o*NM3 + m)*NK3 + k] = s;    // coalesced over k
    } else {
        // symmetrize u2 -> g_u2s[o][k][m], pair order (j,i)
        int tid = (blk-SYM3_BLKS-1)*256 + t;   // 0..1023 = 4 * 256
        if (tid >= OT*256) return;
        int o = tid >> 8;
        int r = tid & 255;
        int i = (r >> 4) & 15, j = r & 15;
        if (i > j) return;
        int m = j*(j+1)/2 + i;
        for (int k = 0; k < NK2; k++) {
            float s;
            if (o == 0) {
                s = u2_0[(i*Dd + j)*NK2 + k];
                if (i != j) s += u2_0[(j*Dd + i)*NK2 + k];
            } else {
                s = u2_1[(((o-1)*Dd + i)*Dd + j)*NK2 + k];
                if (i != j) s += u2_1[(((o-1)*Dd + j)*Dd + i)*NK2 + k];
            }
            g_u2s[(o*NK2 + k)*NM2 + m] = s;
        }
    }
}

// ---------------- fused fold: species weights into bases ----------------
// fold3: smem-tiled. 104 CTAs = 4 species x 13 m-tiles(64) x 2 c-halves(64).
#define F3_BLKS 104
#define F2_BLKS (Ss*Cc*NM2/256)   // 272
#define F1_BLKS (Ss*Cc*Dd/256)    // 32

__global__ void __launch_bounds__(256) k_fold(
        const float* __restrict__ w3, const float* __restrict__ w2,
        const float* __restrict__ u1_0, const float* __restrict__ u1_1,
        const float* __restrict__ w1) {
    int blk = blockIdx.x;
    int t = threadIdx.x;
    if (blk < F3_BLKS) {
        __shared__ float su[OT][NK3][64];   // 23.5 KB
        __shared__ float sw[2][NK3][64];    // 11.8 KB
        int e  = blk / 26;
        int r  = blk % 26;
        int m0 = (r >> 1) * 64;
        int c0 = (r & 1) * 64;
        for (int idx = t; idx < OT*NK3*64; idx += 256) {
            int k = idx % NK3; int mo = idx / NK3; int m = mo & 63; int o = mo >> 6;
            su[o][k][m] = g_u3s[(o*NM3 + m0 + m)*NK3 + k];   // may over-read into pad
        }
        for (int idx = t; idx < 2*NK3*64; idx += 256) {
            int cw = idx & 63; int sk = idx >> 6; int k = sk % NK3; int s = sk / NK3;
            sw[s][k][cw] = w3[((s*Ss + e)*NK3 + k)*Cc + c0 + cw];
        }
        __syncthreads();
        int m = t & 63;
        int cq = t >> 6;
        bool valid = (m0 + m) < NM3;
        #pragma unroll
        for (int ci = 0; ci < 4; ci++) {
            int cl = cq*16 + ci*4;
            float s00=0,s01=0,s02=0,s03=0, s10=0,s11=0,s12=0,s13=0;
            float s20=0,s21=0,s22=0,s23=0, s30=0,s31=0,s32=0,s33=0;
            #pragma unroll
            for (int k = 0; k < NK3; k++) {
                float u0 = su[0][k][m], u1 = su[1][k][m];
                float u2 = su[2][k][m], u3 = su[3][k][m];
                float4 wa = *reinterpret_cast<float4*>(&sw[0][k][cl]);
                float4 wb = *reinterpret_cast<float4*>(&sw[1][k][cl]);
                s00 += u0*wa.x; s01 += u1*wb.x; s02 += u2*wb.x; s03 += u3*wb.x;
                s10 += u0*wa.y; s11 += u1*wb.y; s12 += u2*wb.y; s13 += u3*wb.y;
                s20 += u0*wa.z; s21 += u1*wb.z; s22 += u2*wb.z; s23 += u3*wb.z;
                s30 += u0*wa.w; s31 += u1*wb.w; s32 += u2*wb.w; s33 += u3*wb.w;
            }
            if (valid) {
                int mm = m0 + m;
                g_uw3s[(e*Cc + c0 + cl + 0)*NM3 + mm] = make_float4(s00,s01,s02,s03);
                g_uw3s[(e*Cc + c0 + cl + 1)*NM3 + mm] = make_float4(s10,s11,s12,s13);
                g_uw3s[(e*Cc + c0 + cl + 2)*NM3 + mm] = make_float4(s20,s21,s22,s23);
                g_uw3s[(e*Cc + c0 + cl + 3)*NM3 + mm] = make_float4(s30,s31,s32,s33);
            }
        }
    } else if (blk < F3_BLKS + F2_BLKS) {
        int tid = (blk - F3_BLKS)*256 + t;
        int m = tid % NM2; int ec = tid / NM2;
        int c = ec % Cc;   int e  = ec / Cc;
        const float* w0  = w2 + ((0*Ss + e)*NK2)*Cc + c;
        const float* w1v = w2 + ((1*Ss + e)*NK2)*Cc + c;
        float s0=0.f, s1=0.f, s2=0.f, s3=0.f;
        #pragma unroll
        for (int k = 0; k < NK2; k++) {
            float a = __ldg(w0 + k*Cc), b = __ldg(w1v + k*Cc);
            s0 += g_u2s[(0*NK2 + k)*NM2 + m]*a;
            s1 += g_u2s[(1*NK2 + k)*NM2 + m]*b;
            s2 += g_u2s[(2*NK2 + k)*NM2 + m]*b;
            s3 += g_u2s[(3*NK2 + k)*NM2 + m]*b;
        }
        g_uw2s[tid] = make_float4(s0,s1,s2,s3);
    } else {
        int tid = (blk - F3_BLKS - F2_BLKS)*256 + t;
        int i = tid % Dd; int ec = tid / Dd;
        int c = ec % Cc;  int e  = ec / Cc;
        float s[OT];
        #pragma unroll
        for (int o = 0; o < OT; o++) {
            int set = (o == 0) ? 0 : 1;
            float acc = 0.f;
            #pragma unroll
            for (int k = 0; k < NK1; k++) {
                float uv = (o == 0) ? u1_0[i*NK1 + k]
                                    : u1_1[(((o-1)*Dd) + i)*NK1 + k];
                acc += uv * w1[((set*Ss + e)*NK1 + k)*Cc + c];
            }
            s[o] = acc;
        }
        g_uw1s[tid] = make_float4(s[0], s[1], s[2], s[3]);
    }
}

// ---------------- main symmetric-contraction kernel (packed f32x2, compact code) ----------------
#define FMA2(acc, a, b) asm("fma.rn.f32x2 %0, %1, %2, %0;" : "+l"(acc) : "l"(a), "l"(b))
#define MUL2(d, a, b)   asm("mul.rn.f32x2 %0, %1, %2;" : "=l"(d) : "l"(a), "l"(b))

__global__ void __launch_bounds__(128) k_main(const float* __restrict__ nf) {
    __shared__ ulonglong2 su3[NM3];     // 13056 B
    __shared__ ulonglong2 su2[NM2];     //  2176 B
    __shared__ ulonglong2 su1[Dd];      //   256 B
    int c = blockIdx.x, e = blockIdx.y, half = blockIdx.z;
    int t = threadIdx.x;
    int ec = e*Cc + c;
    const ulonglong2* G3 = reinterpret_cast<const ulonglong2*>(g_uw3s) + ec*NM3;
    const ulonglong2* G2 = reinterpret_cast<const ulonglong2*>(g_uw2s) + ec*NM2;
    const ulonglong2* G1 = reinterpret_cast<const ulonglong2*>(g_uw1s) + ec*Dd;
    for (int idx = t; idx < NM3; idx += 128) su3[idx] = G3[idx];
    for (int idx = t; idx < NM2; idx += 128) su2[idx] = G2[idx];
    if (t < Dd) su1[t] = G1[t];
    __syncthreads();
    int n = g_count[e];
    int off = 0;
    for (int q = 0; q < Ss; q++) if (q < e) off += g_count[q];
    for (int base = half*128; base < n; base += 256) {
        int li = base + t;
        if (li >= n) continue;            // no barriers below: safe divergence
        int p = off + li;
        int b = g_pb[p];
        const float4* src = reinterpret_cast<const float4*>(nf + (b*Cc + c)*Dd);
        float4 v0 = src[0], v1 = src[1], v2 = src[2], v3 = src[3];
        float x[16] = {v0.x,v0.y,v0.z,v0.w, v1.x,v1.y,v1.z,v1.w,
                       v2.x,v2.y,v2.z,v2.w, v3.x,v3.y,v3.z,v3.w};
        u64 xd[16];                        // {x_i, x_i} packed
        #pragma unroll
        for (int i = 0; i < 16; i++) {
            unsigned xi = __float_as_uint(x[i]);
            asm("mov.b64 %0, {%1, %1};" : "=l"(xd[i]) : "r"(xi));
        }
        u64 acc01 = 0ull, acc23 = 0ull;    // {a0,a1}, {a2,a3}
        int m3 = 0, m2 = 0;
        #pragma unroll
        for (int j = 0; j < 16; j++) {     // unrolled: (16-j) known per copy
            u64 xj = xd[j];
            ulonglong2 u1r = su1[j];
            FMA2(acc01, u1r.x, xj);
            FMA2(acc23, u1r.y, xj);
            const int w = 16 - j;
            #pragma unroll 1
            for (int i = 0; i <= j; i++) { // rolled: keeps code small
                u64 xx; MUL2(xx, xd[i], xj);
                ulonglong2 u2r = su2[m2 + i];
                u64 d01 = u2r.x, d23 = u2r.y;    // dot = u2 + sum_l u3*x_l
                const ulonglong2* s3 = &su3[m3 + i*w];
                #pragma unroll
                for (int l = j; l < 16; l++) {
                    ulonglong2 u = s3[l - j];     // LDS.128 broadcast
                    FMA2(d01, u.x, xd[l]);
                    FMA2(d23, u.y, xd[l]);
                }
                FMA2(acc01, xx, d01);            // acc += xx * dot
                FMA2(acc23, xx, d23);
            }
            m2 += j + 1;
            m3 += (j + 1) * w;
        }
        unsigned r0, r1, r2, r3;
        asm("mov.b64 {%0,%1}, %2;" : "=r"(r0), "=r"(r1) : "l"(acc01));
        asm("mov.b64 {%0,%1}, %2;" : "=r"(r2), "=r"(r3) : "l"(acc23));
        g_Y[(0*Cc + c)*Bn + p] = __uint_as_float(r0);   // coalesced: p = off+base+t
        g_Y[(1*Cc + c)*Bn + p] = __uint_as_float(r1);
        g_Y[(2*Cc + c)*Bn + p] = __uint_as_float(r2);
        g_Y[(3*Cc + c)*Bn + p] = __uint_as_float(r3);
    }
}

// ---------------- final equivariant linear (channel mix) ----------------
// W via LDG (64KB, L1-resident, shared across CTAs); only Ys (4KB) in smem.
// Grid (128 p-tiles of 8, 4 o), block 128. Thread: 2 rows x 4 cols.
__global__ void __launch_bounds__(128) k_linear(const float* __restrict__ wlin,
                                                float* __restrict__ out) {
    __shared__ float Ys[Cc*8];
    int o  = blockIdx.y;
    int p0 = blockIdx.x * 8;
    int set = (o == 0) ? 0 : 1;
    int t  = threadIdx.x;
    for (int idx = t; idx < Cc*8; idx += 128) {
        int cc = idx >> 3, pp = idx & 7;
        Ys[cc*8 + pp] = g_Y[(o*Cc + cc)*Bn + p0 + pp];
    }
    __syncthreads();
    int pq = t & 3;           // 4 row-slots x 2 rows = 8
    int nq = t >> 2;          // 32 col-slots x 4 cols = 128
    const float4* W = reinterpret_cast<const float4*>(wlin + set*Cc*Cc) + nq;
    float a00=0,a01=0,a02=0,a03=0, a10=0,a11=0,a12=0,a13=0;
    #pragma unroll 8
    for (int cc = 0; cc < Cc; cc++) {
        float2 y = *reinterpret_cast<const float2*>(&Ys[cc*8 + pq*2]);
        float4 w = __ldg(&W[cc*(Cc/4)]);
        a00 += y.x*w.x; a01 += y.x*w.y; a02 += y.x*w.z; a03 += y.x*w.w;
        a10 += y.y*w.x; a11 += y.y*w.y; a12 += y.y*w.z; a13 += y.y*w.w;
    }
    const float scale = 0.08838834764831845f;    // 1/sqrt(128)
    a00*=scale; a01*=scale; a02*=scale; a03*=scale;
    a10*=scale; a11*=scale; a12*=scale; a13*=scale;
    int p_a = p0 + pq*2;
    int b_a = g_pb[p_a];
    int b_b = g_pb[p_a + 1];
    if (o == 0) {
        *reinterpret_cast<float4*>(&out[b_a*512 + nq*4]) = make_float4(a00,a01,a02,a03);
        *reinterpret_cast<float4*>(&out[b_b*512 + nq*4]) = make_float4(a10,a11,a12,a13);
    } else {
        int op = o - 1;
        out[b_a*512 + 128 + (nq*4 + 0)*3 + op] = a00;
        out[b_a*512 + 128 + (nq*4 + 1)*3 + op] = a01;
        out[b_a*512 + 128 + (nq*4 + 2)*3 + op] = a02;
        out[b_a*512 + 128 + (nq*4 + 3)*3 + op] = a03;
        out[b_b*512 + 128 + (nq*4 + 0)*3 + op] = a10;
        out[b_b*512 + 128 + (nq*4 + 1)*3 + op] = a11;
        out[b_b*512 + 128 + (nq*4 + 2)*3 + op] = a12;
        out[b_b*512 + 128 + (nq*4 + 3)*3 + op] = a13;
    }
}

// ---------------- launch ----------------
extern "C" void kernel_launch(void* const* d_in, const int* in_sizes, int n_in,
                              void* d_out, int out_size) {
    const float* nf   = (const float*)d_in[0];
    const float* u3_0 = (const float*)d_in[1];
    const float* u3_1 = (const float*)d_in[2];
    const float* u2_0 = (const float*)d_in[3];
    const float* u2_1 = (const float*)d_in[4];
    const float* u1_0 = (const float*)d_in[5];
    const float* u1_1 = (const float*)d_in[6];
    const float* w3   = (const float*)d_in[7];
    const float* w2   = (const float*)d_in[8];
    const float* w1   = (const float*)d_in[9];
    const float* wl   = (const float*)d_in[10];
    const int*   sp   = (const int*)d_in[11];
    float* out = (float*)d_out;

    k_prep<<<1 + SYM3_BLKS + 4, 256>>>(sp, u3_0, u3_1, u2_0, u2_1);
    k_fold<<<F3_BLKS + F2_BLKS + F1_BLKS, 256>>>(w3, w2, u1_0, u1_1, w1);
    k_main<<<dim3(Cc, Ss, 2), 128>>>(nf);
    k_linear<<<dim3(Bn/8, 4), 128>>>(wl, out);
}

// round 6
// speedup vs baseline: 2.1388x; 1.0887x over previous
#include <cuda_runtime.h>

#define Bn 1024
#define Cc 128
#define Dd 16
#define Ss 4
#define NK3 23
#define NK2 5
#define NK1 2
#define NM3 816   // # monomials, ordered by (j, i, l): m = off3[j] + i*(16-j) + (l-j)
#define NM2 136   // # pairs, ordered by (j, i): m = j(j+1)/2 + i
#define OT 4      // total output irrep components: 1 (0e) + 3 (1o)

typedef unsigned long long u64;

// ---------------- scratch (device globals; no allocation allowed) ----------------
__device__ float  g_u3s[OT*NM3*NK3 + 512]; // symmetrized u3, layout [o][m][k] (+pad for tile over-read)
__device__ float  g_u2s[OT*NK2*NM2];       // symmetrized u2, layout [o][k][m]
__device__ float4 g_uw3s[Ss*Cc*NM3];       // per-(species,channel) weighted basis, float4 over o
__device__ float4 g_uw2s[Ss*Cc*NM2];
__device__ float4 g_uw1s[Ss*Cc*Dd];
__device__ float  g_Y[OT*Cc*Bn];           // y[o][c][p]  (p = species-compact position)
__device__ int    g_count[Ss];
__device__ int    g_list[Ss*Bn];
__device__ int    g_pb[Bn];                // compact position -> node index

// ---------------- fused prep: species sort/compact + symmetrize u3/u2 ----------------
__device__ __forceinline__ float u3at(const float* __restrict__ u3_0,
                                      const float* __restrict__ u3_1,
                                      int o, int a, int b, int c, int k) {
    if (o == 0) return u3_0[((a*Dd + b)*Dd + c)*NK3 + k];
    return u3_1[((((o-1)*Dd + a)*Dd + b)*Dd + c)*NK3 + k];
}

// prep grid: blk0 = sort; blk 1..294 = sym3 (thread per (o,m,k), coalesced); blk 295..298 = sym2
#define SYM3_BLKS 294
__global__ void k_prep(const int* __restrict__ sp,
                       const float* __restrict__ u3_0, const float* __restrict__ u3_1,
                       const float* __restrict__ u2_0, const float* __restrict__ u2_1) {
    int blk = blockIdx.x;
    int t = threadIdx.x;                 // 256 threads
    if (blk == 0) {
        // species counting-sort + compaction (single block so ordering is safe)
        if (t < Ss) g_count[t] = 0;
        __syncthreads();
        for (int b = t; b < Bn; b += 256) {
            int e = sp[b];
            int pos = atomicAdd(&g_count[e], 1);
            g_list[e*Bn + pos] = b;
        }
        __syncthreads();
        int off = 0;
        for (int e = 0; e < Ss; e++) {
            int n = g_count[e];
            for (int i = t; i < n; i += 256) g_pb[off + i] = g_list[e*Bn + i];
            off += n;
        }
    } else if (blk <= SYM3_BLKS) {
        // symmetrize u3 -> g_u3s[o][m][k], thread per (o,m,k)
        int tid = (blk-1)*256 + t;
        if (tid >= OT*NM3*NK3) return;
        int k  = tid % NK3;
        int om = tid / NK3;
        int m  = om % NM3;
        int o  = om / NM3;
        // decode m -> (i,j,l) in (j,i,l) ordering
        const int off3[17] = {0,16,46,88,140,200,266,336,408,480,550,616,676,728,770,800,816};
        int j = 0;
        #pragma unroll
        for (int q = 1; q < 16; q++) if (m >= off3[q]) j = q;
        int r = m - off3[j];
        int w = 16 - j;
        int i = r / w;
        int l = j + r % w;
        int P[6][3] = {{i,j,l},{i,l,j},{j,i,l},{j,l,i},{l,i,j},{l,j,i}};
        float s = 0.f;
        #pragma unroll
        for (int p = 0; p < 6; p++) {
            bool dup = false;
            for (int q = 0; q < p; q++)
                if (P[q][0]==P[p][0] && P[q][1]==P[p][1] && P[q][2]==P[p][2]) { dup = true; break; }
            if (!dup) s += u3at(u3_0, u3_1, o, P[p][0], P[p][1], P[p][2], k);
        }
        g_u3s[(o*NM3 + m)*NK3 + k] = s;    // coalesced over k
    } else {
        // symmetrize u2 -> g_u2s[o][k][m], pair order (j,i)
        int tid = (blk-SYM3_BLKS-1)*256 + t;   // 0..1023 = 4 * 256
        if (tid >= OT*256) return;
        int o = tid >> 8;
        int r = tid & 255;
        int i = (r >> 4) & 15, j = r & 15;
        if (i > j) return;
        int m = j*(j+1)/2 + i;
        for (int k = 0; k < NK2; k++) {
            float s;
            if (o == 0) {
                s = u2_0[(i*Dd + j)*NK2 + k];
                if (i != j) s += u2_0[(j*Dd + i)*NK2 + k];
            } else {
                s = u2_1[(((o-1)*Dd + i)*Dd + j)*NK2 + k];
                if (i != j) s += u2_1[(((o-1)*Dd + j)*Dd + i)*NK2 + k];
            }
            g_u2s[(o*NK2 + k)*NM2 + m] = s;
        }
    }
}

// ---------------- fused fold: species weights into bases ----------------
// fold3: smem-tiled. 104 CTAs = 4 species x 13 m-tiles(64) x 2 c-halves(64).
#define F3_BLKS 104
#define F2_BLKS (Ss*Cc*NM2/256)   // 272
#define F1_BLKS (Ss*Cc*Dd/256)    // 32

__global__ void __launch_bounds__(256) k_fold(
        const float* __restrict__ w3, const float* __restrict__ w2,
        const float* __restrict__ u1_0, const float* __restrict__ u1_1,
        const float* __restrict__ w1) {
    int blk = blockIdx.x;
    int t = threadIdx.x;
    if (blk < F3_BLKS) {
        __shared__ float su[OT][NK3][64];   // 23.5 KB
        __shared__ float sw[2][NK3][64];    // 11.8 KB
        int e  = blk / 26;
        int r  = blk % 26;
        int m0 = (r >> 1) * 64;
        int c0 = (r & 1) * 64;
        for (int idx = t; idx < OT*NK3*64; idx += 256) {
            int k = idx % NK3; int mo = idx / NK3; int m = mo & 63; int o = mo >> 6;
            su[o][k][m] = g_u3s[(o*NM3 + m0 + m)*NK3 + k];   // may over-read into pad
        }
        for (int idx = t; idx < 2*NK3*64; idx += 256) {
            int cw = idx & 63; int sk = idx >> 6; int k = sk % NK3; int s = sk / NK3;
            sw[s][k][cw] = w3[((s*Ss + e)*NK3 + k)*Cc + c0 + cw];
        }
        __syncthreads();
        int m = t & 63;
        int cq = t >> 6;
        bool valid = (m0 + m) < NM3;
        #pragma unroll
        for (int ci = 0; ci < 4; ci++) {
            int cl = cq*16 + ci*4;
            float s00=0,s01=0,s02=0,s03=0, s10=0,s11=0,s12=0,s13=0;
            float s20=0,s21=0,s22=0,s23=0, s30=0,s31=0,s32=0,s33=0;
            #pragma unroll
            for (int k = 0; k < NK3; k++) {
                float u0 = su[0][k][m], u1 = su[1][k][m];
                float u2 = su[2][k][m], u3 = su[3][k][m];
                float4 wa = *reinterpret_cast<float4*>(&sw[0][k][cl]);
                float4 wb = *reinterpret_cast<float4*>(&sw[1][k][cl]);
                s00 += u0*wa.x; s01 += u1*wb.x; s02 += u2*wb.x; s03 += u3*wb.x;
                s10 += u0*wa.y; s11 += u1*wb.y; s12 += u2*wb.y; s13 += u3*wb.y;
                s20 += u0*wa.z; s21 += u1*wb.z; s22 += u2*wb.z; s23 += u3*wb.z;
                s30 += u0*wa.w; s31 += u1*wb.w; s32 += u2*wb.w; s33 += u3*wb.w;
            }
            if (valid) {
                int mm = m0 + m;
                g_uw3s[(e*Cc + c0 + cl + 0)*NM3 + mm] = make_float4(s00,s01,s02,s03);
                g_uw3s[(e*Cc + c0 + cl + 1)*NM3 + mm] = make_float4(s10,s11,s12,s13);
                g_uw3s[(e*Cc + c0 + cl + 2)*NM3 + mm] = make_float4(s20,s21,s22,s23);
                g_uw3s[(e*Cc + c0 + cl + 3)*NM3 + mm] = make_float4(s30,s31,s32,s33);
            }
        }
    } else if (blk < F3_BLKS + F2_BLKS) {
        int tid = (blk - F3_BLKS)*256 + t;
        int m = tid % NM2; int ec = tid / NM2;
        int c = ec % Cc;   int e  = ec / Cc;
        const float* w0  = w2 + ((0*Ss + e)*NK2)*Cc + c;
        const float* w1v = w2 + ((1*Ss + e)*NK2)*Cc + c;
        float s0=0.f, s1=0.f, s2=0.f, s3=0.f;
        #pragma unroll
        for (int k = 0; k < NK2; k++) {
            float a = __ldg(w0 + k*Cc), b = __ldg(w1v + k*Cc);
            s0 += g_u2s[(0*NK2 + k)*NM2 + m]*a;
            s1 += g_u2s[(1*NK2 + k)*NM2 + m]*b;
            s2 += g_u2s[(2*NK2 + k)*NM2 + m]*b;
            s3 += g_u2s[(3*NK2 + k)*NM2 + m]*b;
        }
        g_uw2s[tid] = make_float4(s0,s1,s2,s3);
    } else {
        int tid = (blk - F3_BLKS - F2_BLKS)*256 + t;
        int i = tid % Dd; int ec = tid / Dd;
        int c = ec % Cc;  int e  = ec / Cc;
        float s[OT];
        #pragma unroll
        for (int o = 0; o < OT; o++) {
            int set = (o == 0) ? 0 : 1;
            float acc = 0.f;
            #pragma unroll
            for (int k = 0; k < NK1; k++) {
                float uv = (o == 0) ? u1_0[i*NK1 + k]
                                    : u1_1[(((o-1)*Dd) + i)*NK1 + k];
                acc += uv * w1[((set*Ss + e)*NK1 + k)*Cc + c];
            }
            s[o] = acc;
        }
        g_uw1s[tid] = make_float4(s[0], s[1], s[2], s[3]);
    }
}

// ---------------- main symmetric-contraction kernel (packed f32x2, compact code) ----------------
#define FMA2(acc, a, b) asm("fma.rn.f32x2 %0, %1, %2, %0;" : "+l"(acc) : "l"(a), "l"(b))
#define MUL2(d, a, b)   asm("mul.rn.f32x2 %0, %1, %2;" : "=l"(d) : "l"(a), "l"(b))

__global__ void __launch_bounds__(128) k_main(const float* __restrict__ nf) {
    __shared__ ulonglong2 su3[NM3];     // 13056 B
    __shared__ ulonglong2 su2[NM2];     //  2176 B
    __shared__ ulonglong2 su1[Dd];      //   256 B
    int c = blockIdx.x, e = blockIdx.y, half = blockIdx.z;
    int t = threadIdx.x;
    int ec = e*Cc + c;
    const ulonglong2* G3 = reinterpret_cast<const ulonglong2*>(g_uw3s) + ec*NM3;
    const ulonglong2* G2 = reinterpret_cast<const ulonglong2*>(g_uw2s) + ec*NM2;
    const ulonglong2* G1 = reinterpret_cast<const ulonglong2*>(g_uw1s) + ec*Dd;
    for (int idx = t; idx < NM3; idx += 128) su3[idx] = G3[idx];
    for (int idx = t; idx < NM2; idx += 128) su2[idx] = G2[idx];
    if (t < Dd) su1[t] = G1[t];
    __syncthreads();
    int n = g_count[e];
    int off = 0;
    for (int q = 0; q < Ss; q++) if (q < e) off += g_count[q];
    for (int base = half*128; base < n; base += 256) {
        int li = base + t;
        if (li >= n) continue;            // no barriers below: safe divergence
        int p = off + li;
        int b = g_pb[p];
        const float4* src = reinterpret_cast<const float4*>(nf + (b*Cc + c)*Dd);
        float4 v0 = src[0], v1 = src[1], v2 = src[2], v3 = src[3];
        float x[16] = {v0.x,v0.y,v0.z,v0.w, v1.x,v1.y,v1.z,v1.w,
                       v2.x,v2.y,v2.z,v2.w, v3.x,v3.y,v3.z,v3.w};
        u64 xd[16];                        // {x_i, x_i} packed
        #pragma unroll
        for (int i = 0; i < 16; i++) {
            unsigned xi = __float_as_uint(x[i]);
            asm("mov.b64 %0, {%1, %1};" : "=l"(xd[i]) : "r"(xi));
        }
        u64 acc01 = 0ull, acc23 = 0ull;    // {a0,a1}, {a2,a3}
        int m3 = 0, m2 = 0;
        #pragma unroll
        for (int j = 0; j < 16; j++) {     // unrolled: (16-j) known per copy
            u64 xj = xd[j];
            ulonglong2 u1r = su1[j];
            FMA2(acc01, u1r.x, xj);
            FMA2(acc23, u1r.y, xj);
            const int w = 16 - j;
            #pragma unroll 1
            for (int i = 0; i <= j; i++) { // rolled: keeps code small
                u64 xx; MUL2(xx, xd[i], xj);
                ulonglong2 u2r = su2[m2 + i];
                u64 d01 = u2r.x, d23 = u2r.y;    // dot = u2 + sum_l u3*x_l
                const ulonglong2* s3 = &su3[m3 + i*w];
                #pragma unroll
                for (int l = j; l < 16; l++) {
                    ulonglong2 u = s3[l - j];     // LDS.128 broadcast
                    FMA2(d01, u.x, xd[l]);
                    FMA2(d23, u.y, xd[l]);
                }
                FMA2(acc01, xx, d01);            // acc += xx * dot
                FMA2(acc23, xx, d23);
            }
            m2 += j + 1;
            m3 += (j + 1) * w;
        }
        unsigned r0, r1, r2, r3;
        asm("mov.b64 {%0,%1}, %2;" : "=r"(r0), "=r"(r1) : "l"(acc01));
        asm("mov.b64 {%0,%1}, %2;" : "=r"(r2), "=r"(r3) : "l"(acc23));
        g_Y[(0*Cc + c)*Bn + p] = __uint_as_float(r0);   // coalesced: p = off+base+t
        g_Y[(1*Cc + c)*Bn + p] = __uint_as_float(r1);
        g_Y[(2*Cc + c)*Bn + p] = __uint_as_float(r2);
        g_Y[(3*Cc + c)*Bn + p] = __uint_as_float(r3);
    }
}

// ---------------- final equivariant linear (channel mix) ----------------
// Whole K=128 in dynamic smem, ONE barrier, exactly one wave (128 CTAs).
// Grid (32 p-tiles of 32, 4 o), block 256. Thread: 4 rows x 4 cols.
#define LIN_SMEM (Cc*Cc*4 + Cc*32*4)   // Ws 64KB + Ys 16KB = 81920 B
__global__ void __launch_bounds__(256) k_linear(const float* __restrict__ wlin,
                                                float* __restrict__ out) {
    extern __shared__ float sm[];
    float* Ws = sm;              // [128][128]
    float* Ys = sm + Cc*Cc;      // [128][32]
    int o  = blockIdx.y;
    int p0 = blockIdx.x * 32;
    int set = (o == 0) ? 0 : 1;
    int t  = threadIdx.x;
    const float4* wsrc = reinterpret_cast<const float4*>(wlin + set*Cc*Cc);
    float4* wdst = reinterpret_cast<float4*>(Ws);
    #pragma unroll
    for (int idx = t; idx < Cc*Cc/4; idx += 256) wdst[idx] = wsrc[idx];
    #pragma unroll
    for (int idx = t; idx < Cc*32; idx += 256) {
        int cc = idx >> 5, pp = idx & 31;
        Ys[cc*32 + pp] = g_Y[(o*Cc + cc)*Bn + p0 + pp];
    }
    __syncthreads();
    int tp = t & 7;           // 8 row-slots x 4 rows = 32
    int tn = t >> 3;          // 32 col-slots x 4 cols = 128
    float a0x=0,a0y=0,a0z=0,a0w=0, a1x=0,a1y=0,a1z=0,a1w=0;
    float a2x=0,a2y=0,a2z=0,a2w=0, a3x=0,a3y=0,a3z=0,a3w=0;
    #pragma unroll 8
    for (int cc = 0; cc < Cc; cc++) {
        float4 y = *reinterpret_cast<const float4*>(&Ys[cc*32 + tp*4]);   // broadcast-dedup
        float4 w = *reinterpret_cast<const float4*>(&Ws[cc*Cc + tn*4]);   // broadcast-dedup
        a0x += y.x*w.x; a0y += y.x*w.y; a0z += y.x*w.z; a0w += y.x*w.w;
        a1x += y.y*w.x; a1y += y.y*w.y; a1z += y.y*w.z; a1w += y.y*w.w;
        a2x += y.z*w.x; a2y += y.z*w.y; a2z += y.z*w.z; a2w += y.z*w.w;
        a3x += y.w*w.x; a3y += y.w*w.y; a3z += y.w*w.z; a3w += y.w*w.w;
    }
    const float scale = 0.08838834764831845f;    // 1/sqrt(128)
    float4 r0 = make_float4(a0x*scale, a0y*scale, a0z*scale, a0w*scale);
    float4 r1 = make_float4(a1x*scale, a1y*scale, a1z*scale, a1w*scale);
    float4 r2 = make_float4(a2x*scale, a2y*scale, a2z*scale, a2w*scale);
    float4 r3 = make_float4(a3x*scale, a3y*scale, a3z*scale, a3w*scale);
    int p_a = p0 + tp*4;
    int b0 = g_pb[p_a + 0], b1 = g_pb[p_a + 1], b2 = g_pb[p_a + 2], b3 = g_pb[p_a + 3];
    if (o == 0) {
        *reinterpret_cast<float4*>(&out[b0*512 + tn*4]) = r0;
        *reinterpret_cast<float4*>(&out[b1*512 + tn*4]) = r1;
        *reinterpret_cast<float4*>(&out[b2*512 + tn*4]) = r2;
        *reinterpret_cast<float4*>(&out[b3*512 + tn*4]) = r3;
    } else {
        int op = o - 1;
        float* o0 = &out[b0*512 + 128 + op];
        float* o1 = &out[b1*512 + 128 + op];
        float* o2 = &out[b2*512 + 128 + op];
        float* o3 = &out[b3*512 + 128 + op];
        o0[(tn*4+0)*3] = r0.x; o0[(tn*4+1)*3] = r0.y; o0[(tn*4+2)*3] = r0.z; o0[(tn*4+3)*3] = r0.w;
        o1[(tn*4+0)*3] = r1.x; o1[(tn*4+1)*3] = r1.y; o1[(tn*4+2)*3] = r1.z; o1[(tn*4+3)*3] = r1.w;
        o2[(tn*4+0)*3] = r2.x; o2[(tn*4+1)*3] = r2.y; o2[(tn*4+2)*3] = r2.z; o2[(tn*4+3)*3] = r2.w;
        o3[(tn*4+0)*3] = r3.x; o3[(tn*4+1)*3] = r3.y; o3[(tn*4+2)*3] = r3.z; o3[(tn*4+3)*3] = r3.w;
    }
}

// ---------------- launch ----------------
extern "C" void kernel_launch(void* const* d_in, const int* in_sizes, int n_in,
                              void* d_out, int out_size) {
    const float* nf   = (const float*)d_in[0];
    const float* u3_0 = (const float*)d_in[1];
    const float* u3_1 = (const float*)d_in[2];
    const float* u2_0 = (const float*)d_in[3];
    const float* u2_1 = (const float*)d_in[4];
    const float* u1_0 = (const float*)d_in[5];
    const float* u1_1 = (const float*)d_in[6];
    const float* w3   = (const float*)d_in[7];
    const float* w2   = (const float*)d_in[8];
    const float* w1   = (const float*)d_in[9];
    const float* wl   = (const float*)d_in[10];
    const int*   sp   = (const int*)d_in[11];
    float* out = (float*)d_out;

    cudaFuncSetAttribute(k_linear, cudaFuncAttributeMaxDynamicSharedMemorySize, LIN_SMEM);

    k_prep<<<1 + SYM3_BLKS + 4, 256>>>(sp, u3_0, u3_1, u2_0, u2_1);
    k_fold<<<F3_BLKS + F2_BLKS + F1_BLKS, 256>>>(w3, w2, u1_0, u1_1, w1);
    k_main<<<dim3(Cc, Ss, 2), 128>>>(nf);
    k_linear<<<dim3(Bn/32, 4), 256, LIN_SMEM>>>(wl, out);
}

// round 7
// speedup vs baseline: 2.1502x; 1.0053x over previous
#include <cuda_runtime.h>

#define Bn 1024
#define Cc 128
#define Dd 16
#define Ss 4
#define NK3 23
#define NK2 5
#define NK1 2
#define NM3 816   // # monomials, ordered by (j, i, l): m = off3[j] + i*(16-j) + (l-j)
#define NM2 136   // # pairs, ordered by (j, i): m = j(j+1)/2 + i
#define OT 4      // total output irrep components: 1 (0e) + 3 (1o)

typedef unsigned long long u64;

// ---------------- scratch (device globals; no allocation allowed) ----------------
__device__ float  g_u3s[OT*NM3*NK3 + 512]; // symmetrized u3, layout [o][m][k] (+pad for tile over-read)
__device__ float  g_u2s[OT*NK2*NM2];       // symmetrized u2, layout [o][k][m]
__device__ float4 g_uw3s[Ss*Cc*NM3];       // per-(species,channel) weighted basis, float4 over o
__device__ float4 g_uw2s[Ss*Cc*NM2];
__device__ float4 g_uw1s[Ss*Cc*Dd];
__device__ float  g_Y[OT*Cc*Bn];           // y[o][c][p]  (p = species-compact position)
__device__ int    g_count[Ss];
__device__ int    g_list[Ss*Bn];
__device__ int    g_pb[Bn];                // compact position -> node index

// ---------------- fused prep: species sort/compact + symmetrize u3/u2 ----------------
__device__ __forceinline__ float u3at(const float* __restrict__ u3_0,
                                      const float* __restrict__ u3_1,
                                      int o, int a, int b, int c, int k) {
    if (o == 0) return u3_0[((a*Dd + b)*Dd + c)*NK3 + k];
    return u3_1[((((o-1)*Dd + a)*Dd + b)*Dd + c)*NK3 + k];
}

// prep grid: blk0 = sort; blk 1..294 = sym3 (thread per (o,m,k), coalesced); blk 295..298 = sym2
#define SYM3_BLKS 294
__global__ void k_prep(const int* __restrict__ sp,
                       const float* __restrict__ u3_0, const float* __restrict__ u3_1,
                       const float* __restrict__ u2_0, const float* __restrict__ u2_1) {
    int blk = blockIdx.x;
    int t = threadIdx.x;                 // 256 threads
    if (blk == 0) {
        // species counting-sort + compaction (single block so ordering is safe)
        if (t < Ss) g_count[t] = 0;
        __syncthreads();
        for (int b = t; b < Bn; b += 256) {
            int e = sp[b];
            int pos = atomicAdd(&g_count[e], 1);
            g_list[e*Bn + pos] = b;
        }
        __syncthreads();
        int off = 0;
        for (int e = 0; e < Ss; e++) {
            int n = g_count[e];
            for (int i = t; i < n; i += 256) g_pb[off + i] = g_list[e*Bn + i];
            off += n;
        }
    } else if (blk <= SYM3_BLKS) {
        // symmetrize u3 -> g_u3s[o][m][k], thread per (o,m,k)
        int tid = (blk-1)*256 + t;
        if (tid >= OT*NM3*NK3) return;
        int k  = tid % NK3;
        int om = tid / NK3;
        int m  = om % NM3;
        int o  = om / NM3;
        // decode m -> (i,j,l) in (j,i,l) ordering
        const int off3[17] = {0,16,46,88,140,200,266,336,408,480,550,616,676,728,770,800,816};
        int j = 0;
        #pragma unroll
        for (int q = 1; q < 16; q++) if (m >= off3[q]) j = q;
        int r = m - off3[j];
        int w = 16 - j;
        int i = r / w;
        int l = j + r % w;
        int P[6][3] = {{i,j,l},{i,l,j},{j,i,l},{j,l,i},{l,i,j},{l,j,i}};
        float s = 0.f;
        #pragma unroll
        for (int p = 0; p < 6; p++) {
            bool dup = false;
            for (int q = 0; q < p; q++)
                if (P[q][0]==P[p][0] && P[q][1]==P[p][1] && P[q][2]==P[p][2]) { dup = true; break; }
            if (!dup) s += u3at(u3_0, u3_1, o, P[p][0], P[p][1], P[p][2], k);
        }
        g_u3s[(o*NM3 + m)*NK3 + k] = s;    // coalesced over k
    } else {
        // symmetrize u2 -> g_u2s[o][k][m], pair order (j,i)
        int tid = (blk-SYM3_BLKS-1)*256 + t;   // 0..1023 = 4 * 256
        if (tid >= OT*256) return;
        int o = tid >> 8;
        int r = tid & 255;
        int i = (r >> 4) & 15, j = r & 15;
        if (i > j) return;
        int m = j*(j+1)/2 + i;
        for (int k = 0; k < NK2; k++) {
            float s;
            if (o == 0) {
                s = u2_0[(i*Dd + j)*NK2 + k];
                if (i != j) s += u2_0[(j*Dd + i)*NK2 + k];
            } else {
                s = u2_1[(((o-1)*Dd + i)*Dd + j)*NK2 + k];
                if (i != j) s += u2_1[(((o-1)*Dd + j)*Dd + i)*NK2 + k];
            }
            g_u2s[(o*NK2 + k)*NM2 + m] = s;
        }
    }
}

// ---------------- fused fold: species weights into bases ----------------
// fold3: smem-tiled. 208 CTAs = 4 species x 13 m-tiles(64) x 4 c-blocks(32).
#define F3_BLKS 208
#define F2_BLKS (Ss*Cc*NM2/256)   // 272
#define F1_BLKS (Ss*Cc*Dd/256)    // 32

__global__ void __launch_bounds__(256) k_fold(
        const float* __restrict__ w3, const float* __restrict__ w2,
        const float* __restrict__ u1_0, const float* __restrict__ u1_1,
        const float* __restrict__ w1) {
    int blk = blockIdx.x;
    int t = threadIdx.x;
    if (blk < F3_BLKS) {
        __shared__ float su[OT][NK3][64];   // 23.5 KB
        __shared__ float sw[2][NK3][32];    //  5.9 KB
        int e  = blk / 52;
        int r  = blk % 52;
        int m0 = (r >> 2) * 64;
        int c0 = (r & 3) * 32;
        for (int idx = t; idx < OT*NK3*64; idx += 256) {
            int k = idx % NK3; int mo = idx / NK3; int m = mo & 63; int o = mo >> 6;
            su[o][k][m] = g_u3s[(o*NM3 + m0 + m)*NK3 + k];   // may over-read into pad
        }
        for (int idx = t; idx < 2*NK3*32; idx += 256) {
            int cw = idx & 31; int sk = idx >> 5; int k = sk % NK3; int s = sk / NK3;
            sw[s][k][cw] = w3[((s*Ss + e)*NK3 + k)*Cc + c0 + cw];
        }
        __syncthreads();
        int m = t & 63;
        int cq = t >> 6;
        bool valid = (m0 + m) < NM3;
        #pragma unroll
        for (int ci = 0; ci < 2; ci++) {
            int cl = cq*8 + ci*4;
            float s00=0,s01=0,s02=0,s03=0, s10=0,s11=0,s12=0,s13=0;
            float s20=0,s21=0,s22=0,s23=0, s30=0,s31=0,s32=0,s33=0;
            #pragma unroll
            for (int k = 0; k < NK3; k++) {
                float u0 = su[0][k][m], u1 = su[1][k][m];
                float u2 = su[2][k][m], u3 = su[3][k][m];
                float4 wa = *reinterpret_cast<float4*>(&sw[0][k][cl]);
                float4 wb = *reinterpret_cast<float4*>(&sw[1][k][cl]);
                s00 += u0*wa.x; s01 += u1*wb.x; s02 += u2*wb.x; s03 += u3*wb.x;
                s10 += u0*wa.y; s11 += u1*wb.y; s12 += u2*wb.y; s13 += u3*wb.y;
                s20 += u0*wa.z; s21 += u1*wb.z; s22 += u2*wb.z; s23 += u3*wb.z;
                s30 += u0*wa.w; s31 += u1*wb.w; s32 += u2*wb.w; s33 += u3*wb.w;
            }
            if (valid) {
                int mm = m0 + m;
                g_uw3s[(e*Cc + c0 + cl + 0)*NM3 + mm] = make_float4(s00,s01,s02,s03);
                g_uw3s[(e*Cc + c0 + cl + 1)*NM3 + mm] = make_float4(s10,s11,s12,s13);
                g_uw3s[(e*Cc + c0 + cl + 2)*NM3 + mm] = make_float4(s20,s21,s22,s23);
                g_uw3s[(e*Cc + c0 + cl + 3)*NM3 + mm] = make_float4(s30,s31,s32,s33);
            }
        }
    } else if (blk < F3_BLKS + F2_BLKS) {
        int tid = (blk - F3_BLKS)*256 + t;
        int m = tid % NM2; int ec = tid / NM2;
        int c = ec % Cc;   int e  = ec / Cc;
        const float* w0  = w2 + ((0*Ss + e)*NK2)*Cc + c;
        const float* w1v = w2 + ((1*Ss + e)*NK2)*Cc + c;
        float s0=0.f, s1=0.f, s2=0.f, s3=0.f;
        #pragma unroll
        for (int k = 0; k < NK2; k++) {
            float a = __ldg(w0 + k*Cc), b = __ldg(w1v + k*Cc);
            s0 += g_u2s[(0*NK2 + k)*NM2 + m]*a;
            s1 += g_u2s[(1*NK2 + k)*NM2 + m]*b;
            s2 += g_u2s[(2*NK2 + k)*NM2 + m]*b;
            s3 += g_u2s[(3*NK2 + k)*NM2 + m]*b;
        }
        g_uw2s[tid] = make_float4(s0,s1,s2,s3);
    } else {
        int tid = (blk - F3_BLKS - F2_BLKS)*256 + t;
        int i = tid % Dd; int ec = tid / Dd;
        int c = ec % Cc;  int e  = ec / Cc;
        float s[OT];
        #pragma unroll
        for (int o = 0; o < OT; o++) {
            int set = (o == 0) ? 0 : 1;
            float acc = 0.f;
            #pragma unroll
            for (int k = 0; k < NK1; k++) {
                float uv = (o == 0) ? u1_0[i*NK1 + k]
                                    : u1_1[(((o-1)*Dd) + i)*NK1 + k];
                acc += uv * w1[((set*Ss + e)*NK1 + k)*Cc + c];
            }
            s[o] = acc;
        }
        g_uw1s[tid] = make_float4(s[0], s[1], s[2], s[3]);
    }
}

// ---------------- main symmetric-contraction kernel (packed f32x2, compact code) ----------------
#define FMA2(acc, a, b) asm("fma.rn.f32x2 %0, %1, %2, %0;" : "+l"(acc) : "l"(a), "l"(b))
#define MUL2(d, a, b)   asm("mul.rn.f32x2 %0, %1, %2;" : "=l"(d) : "l"(a), "l"(b))

__global__ void __launch_bounds__(128) k_main(const float* __restrict__ nf) {
    __shared__ ulonglong2 su3[NM3];     // 13056 B
    __shared__ ulonglong2 su2[NM2];     //  2176 B
    __shared__ ulonglong2 su1[Dd];      //   256 B
    int c = blockIdx.x, e = blockIdx.y, half = blockIdx.z;
    int t = threadIdx.x;
    int ec = e*Cc + c;
    const ulonglong2* G3 = reinterpret_cast<const ulonglong2*>(g_uw3s) + ec*NM3;
    const ulonglong2* G2 = reinterpret_cast<const ulonglong2*>(g_uw2s) + ec*NM2;
    const ulonglong2* G1 = reinterpret_cast<const ulonglong2*>(g_uw1s) + ec*Dd;
    for (int idx = t; idx < NM3; idx += 128) su3[idx] = G3[idx];
    for (int idx = t; idx < NM2; idx += 128) su2[idx] = G2[idx];
    if (t < Dd) su1[t] = G1[t];
    __syncthreads();
    int n = g_count[e];
    int off = 0;
    for (int q = 0; q < Ss; q++) if (q < e) off += g_count[q];
    for (int base = half*128; base < n; base += 256) {
        int li = base + t;
        if (li >= n) continue;            // no barriers below: safe divergence
        int p = off + li;
        int b = g_pb[p];
        const float4* src = reinterpret_cast<const float4*>(nf + (b*Cc + c)*Dd);
        float4 v0 = src[0], v1 = src[1], v2 = src[2], v3 = src[3];
        float x[16] = {v0.x,v0.y,v0.z,v0.w, v1.x,v1.y,v1.z,v1.w,
                       v2.x,v2.y,v2.z,v2.w, v3.x,v3.y,v3.z,v3.w};
        u64 xd[16];                        // {x_i, x_i} packed
        #pragma unroll
        for (int i = 0; i < 16; i++) {
            unsigned xi = __float_as_uint(x[i]);
            asm("mov.b64 %0, {%1, %1};" : "=l"(xd[i]) : "r"(xi));
        }
        u64 acc01 = 0ull, acc23 = 0ull;    // {a0,a1}, {a2,a3}
        int m3 = 0, m2 = 0;
        #pragma unroll
        for (int j = 0; j < 16; j++) {     // unrolled: (16-j) known per copy
            u64 xj = xd[j];
            ulonglong2 u1r = su1[j];
            FMA2(acc01, u1r.x, xj);
            FMA2(acc23, u1r.y, xj);
            const int w = 16 - j;
            #pragma unroll 1
            for (int i = 0; i <= j; i++) { // rolled: keeps code small
                u64 xx; MUL2(xx, xd[i], xj);
                ulonglong2 u2r = su2[m2 + i];
                u64 d01 = u2r.x, d23 = u2r.y;    // dot = u2 + sum_l u3*x_l
                const ulonglong2* s3 = &su3[m3 + i*w];
                #pragma unroll
                for (int l = j; l < 16; l++) {
                    ulonglong2 u = s3[l - j];     // LDS.128 broadcast
                    FMA2(d01, u.x, xd[l]);
                    FMA2(d23, u.y, xd[l]);
                }
                FMA2(acc01, xx, d01);            // acc += xx * dot
                FMA2(acc23, xx, d23);
            }
            m2 += j + 1;
            m3 += (j + 1) * w;
        }
        unsigned r0, r1, r2, r3;
        asm("mov.b64 {%0,%1}, %2;" : "=r"(r0), "=r"(r1) : "l"(acc01));
        asm("mov.b64 {%0,%1}, %2;" : "=r"(r2), "=r"(r3) : "l"(acc23));
        g_Y[(0*Cc + c)*Bn + p] = __uint_as_float(r0);   // coalesced: p = off+base+t
        g_Y[(1*Cc + c)*Bn + p] = __uint_as_float(r1);
        g_Y[(2*Cc + c)*Bn + p] = __uint_as_float(r2);
        g_Y[(3*Cc + c)*Bn + p] = __uint_as_float(r3);
    }
}

// ---------------- final equivariant linear (channel mix) ----------------
// Whole K=128 in dynamic smem, ONE barrier, one wave (128 CTAs), 512 threads
// for latency hiding (4 warps/SMSP). Thread: 2 rows x 4 cols.
#define LIN_SMEM (Cc*Cc*4 + Cc*32*4)   // Ws 64KB + Ys 16KB = 81920 B
__global__ void __launch_bounds__(512) k_linear(const float* __restrict__ wlin,
                                                float* __restrict__ out) {
    extern __shared__ float sm[];
    float* Ws = sm;              // [128][128]
    float* Ys = sm + Cc*Cc;      // [128][32]
    int o  = blockIdx.y;
    int p0 = blockIdx.x * 32;
    int set = (o == 0) ? 0 : 1;
    int t  = threadIdx.x;
    const float4* wsrc = reinterpret_cast<const float4*>(wlin + set*Cc*Cc);
    float4* wdst = reinterpret_cast<float4*>(Ws);
    #pragma unroll
    for (int idx = t; idx < Cc*Cc/4; idx += 512) wdst[idx] = wsrc[idx];
    #pragma unroll
    for (int idx = t; idx < Cc*32; idx += 512) {
        int cc = idx >> 5, pp = idx & 31;
        Ys[cc*32 + pp] = g_Y[(o*Cc + cc)*Bn + p0 + pp];
    }
    __syncthreads();
    int tp = t & 15;          // 16 row-slots x 2 rows = 32
    int tn = t >> 4;          // 32 col-slots x 4 cols = 128
    float a0x=0,a0y=0,a0z=0,a0w=0, a1x=0,a1y=0,a1z=0,a1w=0;
    #pragma unroll 16
    for (int cc = 0; cc < Cc; cc++) {
        float2 y = *reinterpret_cast<const float2*>(&Ys[cc*32 + tp*2]);   // broadcast-dedup
        float4 w = *reinterpret_cast<const float4*>(&Ws[cc*Cc + tn*4]);   // broadcast-dedup
        a0x += y.x*w.x; a0y += y.x*w.y; a0z += y.x*w.z; a0w += y.x*w.w;
        a1x += y.y*w.x; a1y += y.y*w.y; a1z += y.y*w.z; a1w += y.y*w.w;
    }
    const float scale = 0.08838834764831845f;    // 1/sqrt(128)
    float4 r0 = make_float4(a0x*scale, a0y*scale, a0z*scale, a0w*scale);
    float4 r1 = make_float4(a1x*scale, a1y*scale, a1z*scale, a1w*scale);
    int p_a = p0 + tp*2;
    int b0 = g_pb[p_a + 0], b1 = g_pb[p_a + 1];
    if (o == 0) {
        *reinterpret_cast<float4*>(&out[b0*512 + tn*4]) = r0;
        *reinterpret_cast<float4*>(&out[b1*512 + tn*4]) = r1;
    } else {
        int op = o - 1;
        float* o0 = &out[b0*512 + 128 + op];
        float* o1 = &out[b1*512 + 128 + op];
        o0[(tn*4+0)*3] = r0.x; o0[(tn*4+1)*3] = r0.y; o0[(tn*4+2)*3] = r0.z; o0[(tn*4+3)*3] = r0.w;
        o1[(tn*4+0)*3] = r1.x; o1[(tn*4+1)*3] = r1.y; o1[(tn*4+2)*3] = r1.z; o1[(tn*4+3)*3] = r1.w;
    }
}

// ---------------- launch ----------------
extern "C" void kernel_launch(void* const* d_in, const int* in_sizes, int n_in,
                              void* d_out, int out_size) {
    const float* nf   = (const float*)d_in[0];
    const float* u3_0 = (const float*)d_in[1];
    const float* u3_1 = (const float*)d_in[2];
    const float* u2_0 = (const float*)d_in[3];
    const float* u2_1 = (const float*)d_in[4];
    const float* u1_0 = (const float*)d_in[5];
    const float* u1_1 = (const float*)d_in[6];
    const float* w3   = (const float*)d_in[7];
    const float* w2   = (const float*)d_in[8];
    const float* w1   = (const float*)d_in[9];
    const float* wl   = (const float*)d_in[10];
    const int*   sp   = (const int*)d_in[11];
    float* out = (float*)d_out;

    cudaFuncSetAttribute(k_linear, cudaFuncAttributeMaxDynamicSharedMemorySize, LIN_SMEM);

    k_prep<<<1 + SYM3_BLKS + 4, 256>>>(sp, u3_0, u3_1, u2_0, u2_1);
    k_fold<<<F3_BLKS + F2_BLKS + F1_BLKS, 256>>>(w3, w2, u1_0, u1_1, w1);
    k_main<<<dim3(Cc, Ss, 2), 128>>>(nf);
    k_linear<<<dim3(Bn/32, 4), 512, LIN_SMEM>>>(wl, out);
}